// round 4
// baseline (speedup 1.0000x reference)
#include <cuda_runtime.h>
#include <math.h>

#define BB   16
#define HH   128
#define WW   128
#define HWSZ (HH*WW)
#define CSP  63
#define CIN1 32
#define CIN2 64

typedef unsigned long long ull;

__device__ float g_s1[BB*CSP*HWSZ];
__device__ float g_y1[BB*64*HWSZ];
__device__ float g_s2[BB*CSP*HWSZ];
__device__ float g_sp[BB*CSP*HWSZ];
#define PART_STRIDE (4*256*16*2)
__device__ float g_part[3*PART_STRIDE];
__device__ float g_stats[3*CSP*2];

// packed dual-fp32 FMA (SASS FFMA2) — only reachable via PTX f32x2
#define FMA2(d, a, b) asm("fma.rn.f32x2 %0, %1, %2, %0;" : "+l"(d) : "l"(a), "l"(b))
#define PACK2(d, lo, hi) asm("mov.b64 %0, {%1, %2};" : "=l"(d) : "r"(__float_as_uint(lo)), "r"(__float_as_uint(hi)))
#define UNPK2(lo, hi, s) do { unsigned _l,_h; asm("mov.b64 {%0, %1}, %2;" : "=r"(_l), "=r"(_h) : "l"(s)); lo=__uint_as_float(_l); hi=__uint_as_float(_h); } while(0)

// ---------------------------------------------------------------------------
// Direct conv v3 (FFMA2): 32x32 tile, 256 threads, each thread a 2x2 pixel
// quad packed along x. 16 oc per block. 2 input channels per smem stage.
// Weights pre-duplicated {w,w} in smem so the b-operand is a single LDS.64.
// ---------------------------------------------------------------------------
template<int KS, int CIN>
__global__ __launch_bounds__(256, 2)
void conv_k(const float* __restrict__ in, const float* __restrict__ w,
            const float* __restrict__ bias, float* __restrict__ out,
            float* __restrict__ part)
{
    constexpr int TS   = 32;
    constexpr int HALO = (KS == 3) ? 1 : 0;
    constexpr int IT   = TS + 2*HALO;        // 34 or 32
    constexpr int ITP  = IT + 1;             // padded row stride (odd)
    constexpr int KK   = KS*KS;              // 9 or 1
    constexpr int WPAD = (KS == 3) ? 10 : 2; // float2 stride per oc
    constexpr int ROWS = 2 + 2*HALO;         // 4 or 2
    constexpr int COLS = 2 + 2*HALO;         // 4 or 2

    __shared__ __align__(16) float  tile[2][IT*ITP];
    __shared__ __align__(16) float2 wsh2[2][16][WPAD];
    __shared__ float redw[8][16][2];

    const int t   = threadIdx.x;
    const int cx  = t & 15;                  // column-pair index
    const int ry  = t >> 4;                  // row-pair index 0..15
    const int wid = t >> 5;
    const int lx  = cx*2;
    const int ly  = ry*2;
    const int bz  = blockIdx.z;
    const int b   = bz >> 2;
    const int grp = bz & 3;
    const int oc0 = grp * 16;
    const int nOC = (oc0 + 16 <= CSP) ? 16 : (CSP - oc0);
    const int x0  = blockIdx.x * TS;
    const int y0  = blockIdx.y * TS;

    ull acc2[16][2];
#pragma unroll
    for (int o = 0; o < 16; o++) { acc2[o][0] = 0ull; acc2[o][1] = 0ull; }

    for (int st = 0; st < CIN/2; st++) {
        const int ic0 = st*2;
        __syncthreads();
        const float* ip0 = in + (size_t)(b*CIN + ic0) * HWSZ;
        const float* ip1 = ip0 + HWSZ;
        for (int i = t; i < IT*IT; i += 256) {
            int r = i / IT, c = i - r*IT;
            int gy = y0 + r - HALO, gx = x0 + c - HALO;
            bool ok = (gy >= 0 && gy < HH && gx >= 0 && gx < WW);
            int off = gy*WW + gx;
            tile[0][r*ITP + c] = ok ? ip0[off] : 0.f;
            tile[1][r*ITP + c] = ok ? ip1[off] : 0.f;
        }
        for (int i = t; i < 2*16*KK; i += 256) {
            int cc  = i / (16*KK);
            int rem = i - cc*(16*KK);
            int oc  = rem / KK;
            int k   = rem - oc*KK;
            float v = 0.f;
            if (oc0 + oc < CSP)
                v = w[((size_t)(oc0+oc)*CIN + ic0 + cc)*KK + k];
            wsh2[cc][oc][k] = make_float2(v, v);
        }
        __syncthreads();

#pragma unroll
        for (int cc = 0; cc < 2; cc++) {
            // gather ROWSxCOLS window for this 2x2 quad
            float iv[ROWS][COLS];
#pragma unroll
            for (int r = 0; r < ROWS; r++)
#pragma unroll
                for (int c = 0; c < COLS; c++)
                    iv[r][c] = tile[cc][(ly + r)*ITP + lx + c];

            // x-packed pairs: p[r][dx] = {iv[r][dx], iv[r][dx+1]}
            ull p[ROWS][KS];
#pragma unroll
            for (int r = 0; r < ROWS; r++)
#pragma unroll
                for (int dx = 0; dx < KS; dx++)
                    PACK2(p[r][dx], iv[r][dx], iv[r][dx+1]);

#pragma unroll
            for (int oc = 0; oc < 16; oc++) {
                const ull* wq = reinterpret_cast<const ull*>(&wsh2[cc][oc][0]);
                if (KS == 3) {
                    ull wr[9];
#pragma unroll
                    for (int j = 0; j < 9; j++) wr[j] = wq[j];
#pragma unroll
                    for (int dy = 0; dy < 3; dy++)
#pragma unroll
                        for (int dx = 0; dx < 3; dx++) {
                            FMA2(acc2[oc][0], p[dy  ][dx], wr[dy*3+dx]);
                            FMA2(acc2[oc][1], p[dy+1][dx], wr[dy*3+dx]);
                        }
                } else {
                    ull w0 = wq[0];
                    FMA2(acc2[oc][0], p[0][0], w0);
                    FMA2(acc2[oc][1], p[1][0], w0);
                }
            }
        }
    }

    // epilogue: bias, store, deterministic BN partials
#pragma unroll
    for (int oc = 0; oc < 16; oc++) {
        float bv = (oc < nOC) ? bias[oc0 + oc] : 0.f;
        float v[2][2];
        UNPK2(v[0][0], v[0][1], acc2[oc][0]);
        UNPK2(v[1][0], v[1][1], acc2[oc][1]);
        float s = 0.f, q = 0.f;
        float* op = out + (size_t)(b*CSP + oc0 + oc) * HWSZ;
#pragma unroll
        for (int r = 0; r < 2; r++)
#pragma unroll
            for (int c = 0; c < 2; c++) {
                float vv = v[r][c] + bv;
                if (oc < nOC) op[(y0 + ly + r)*WW + x0 + lx + c] = vv;
                s += vv;
                q += vv*vv;
            }
#pragma unroll
        for (int off = 16; off > 0; off >>= 1) {
            s += __shfl_down_sync(0xffffffffu, s, off);
            q += __shfl_down_sync(0xffffffffu, q, off);
        }
        if ((t & 31) == 0) { redw[wid][oc][0] = s; redw[wid][oc][1] = q; }
    }
    __syncthreads();
    if (t < 32) {
        int oc = t >> 1, which = t & 1;
        float s = 0.f;
#pragma unroll
        for (int wgi = 0; wgi < 8; wgi++) s += redw[wgi][oc][which];
        int blkIdx = b*16 + blockIdx.y*4 + blockIdx.x;
        part[((grp*256 + blkIdx)*16 + oc)*2 + which] = s;
    }
}

// ---------------------------------------------------------------------------
__global__ __launch_bounds__(256)
void stats_k(const float* __restrict__ part,
             const float* __restrict__ gamma,
             const float* __restrict__ beta,
             float* __restrict__ stats)
{
    __shared__ double ss[256], qq[256];
    const int c = blockIdx.x;
    const int t = threadIdx.x;
    const int grp = c >> 4, oc = c & 15;
    const float* p = part + ((size_t)(grp*256 + t)*16 + oc)*2;
    ss[t] = (double)p[0];
    qq[t] = (double)p[1];
#pragma unroll
    for (int off = 128; off > 0; off >>= 1) {
        __syncthreads();
        if (t < off) { ss[t] += ss[t+off]; qq[t] += qq[t+off]; }
    }
    if (t == 0) {
        const double n = (double)BB * (double)HWSZ;
        double mu  = ss[0] / n;
        double var = qq[0] / n - mu*mu;
        float rstd = (float)(1.0 / sqrt(var + 1e-5));
        float a  = gamma[c] * rstd;
        float bc = beta[c] - a * (float)mu;
        stats[c*2]   = a;
        stats[c*2+1] = bc;
    }
}

// ---------------------------------------------------------------------------
__global__ __launch_bounds__(256)
void bnrp_k(const float* __restrict__ s1, const float* __restrict__ stats,
            float* __restrict__ y1)
{
    __shared__ float a[CSP], bc[CSP];
    int t = threadIdx.x;
    if (t < CSP) { a[t] = stats[2*t]; bc[t] = stats[2*t+1]; }
    __syncthreads();
    int g = blockIdx.x * 256 + t;
    int b = g >> 14, pix = g & (HWSZ - 1);
    const float* sp_ = s1 + (size_t)b*CSP*HWSZ + pix;
    float* yp = y1 + (size_t)b*64*HWSZ + pix;
    float q = 0.f;
#pragma unroll 9
    for (int c = 0; c < CSP; c++) {
        float v = sp_[(size_t)c*HWSZ];
        float h = fmaf(a[c], v, bc[c]);
        float r = fmaxf(h, 0.f);
        yp[(size_t)(c+1)*HWSZ] = r;
        q = fmaf(r, r, q);
    }
    yp[0] = sqrtf(1.f + q);
}

__global__ __launch_bounds__(256)
void final_k(const float* __restrict__ s2, const float* __restrict__ sp,
             const float* __restrict__ st2, const float* __restrict__ stp,
             float* __restrict__ out)
{
    __shared__ float a2[CSP], b2s[CSP], apv[CSP], bpv[CSP];
    int t = threadIdx.x;
    if (t < CSP) {
        a2[t]  = st2[2*t]; b2s[t] = st2[2*t+1];
        apv[t] = stp[2*t]; bpv[t] = stp[2*t+1];
    }
    __syncthreads();
    int g = blockIdx.x * 256 + t;
    int b = g >> 14, pix = g & (HWSZ - 1);
    const float* p2 = s2 + (size_t)b*CSP*HWSZ + pix;
    const float* pp = sp + (size_t)b*CSP*HWSZ + pix;
    float* op = out + (size_t)b*64*HWSZ + pix;
    float q = 0.f;
#pragma unroll 9
    for (int c = 0; c < CSP; c++) {
        float v2 = p2[(size_t)c*HWSZ];
        float vp = pp[(size_t)c*HWSZ];
        float h = fmaf(a2[c], v2, b2s[c]) + fmaf(apv[c], vp, bpv[c]);
        float r = fmaxf(h, 0.f);
        op[(size_t)(c+1)*HWSZ] = r;
        q = fmaf(r, r, q);
    }
    op[0] = sqrtf(1.f + q);
}

// ---------------------------------------------------------------------------
extern "C" void kernel_launch(void* const* d_in, const int* in_sizes, int n_in,
                              void* d_out, int out_size)
{
    const float* x   = (const float*)d_in[0];
    const float* w1  = (const float*)d_in[1];
    const float* b1  = (const float*)d_in[2];
    const float* g1  = (const float*)d_in[3];
    const float* bt1 = (const float*)d_in[4];
    const float* w2  = (const float*)d_in[5];
    const float* b2  = (const float*)d_in[6];
    const float* g2  = (const float*)d_in[7];
    const float* bt2 = (const float*)d_in[8];
    const float* wp  = (const float*)d_in[9];
    const float* bp  = (const float*)d_in[10];
    const float* gp  = (const float*)d_in[11];
    const float* btp = (const float*)d_in[12];
    float* out = (float*)d_out;

    void *p_s1, *p_y1, *p_s2, *p_sp, *p_part, *p_stats;
    cudaGetSymbolAddress(&p_s1, g_s1);
    cudaGetSymbolAddress(&p_y1, g_y1);
    cudaGetSymbolAddress(&p_s2, g_s2);
    cudaGetSymbolAddress(&p_sp, g_sp);
    cudaGetSymbolAddress(&p_part, g_part);
    cudaGetSymbolAddress(&p_stats, g_stats);
    float* s1 = (float*)p_s1;
    float* y1 = (float*)p_y1;
    float* s2 = (float*)p_s2;
    float* sp = (float*)p_sp;
    float* part  = (float*)p_part;
    float* stats = (float*)p_stats;

    dim3 cg(4, 4, BB*4);
    const int ew_blocks = BB*HWSZ/256;

    conv_k<3, CIN1><<<cg, 256>>>(x, w1, b1, s1, part + 0*PART_STRIDE);
    stats_k<<<CSP, 256>>>(part + 0*PART_STRIDE, g1, bt1, stats + 0*CSP*2);
    bnrp_k<<<ew_blocks, 256>>>(s1, stats + 0*CSP*2, y1);

    conv_k<3, CIN2><<<cg, 256>>>(y1, w2, b2, s2, part + 1*PART_STRIDE);
    conv_k<1, CIN1><<<cg, 256>>>(x, wp, bp, sp, part + 2*PART_STRIDE);
    stats_k<<<CSP, 256>>>(part + 1*PART_STRIDE, g2, bt2, stats + 1*CSP*2);
    stats_k<<<CSP, 256>>>(part + 2*PART_STRIDE, gp, btp, stats + 2*CSP*2);

    final_k<<<ew_blocks, 256>>>(s2, sp, stats + 1*CSP*2, stats + 2*CSP*2, out);
}

// round 6
// speedup vs baseline: 1.9401x; 1.9401x over previous
#include <cuda_runtime.h>
#include <cuda_bf16.h>
#include <math.h>
#include <stdint.h>

#define BB    16
#define HH    128
#define WW    128
#define HWSZ  (HH*WW)
#define NPX   (BB*HWSZ)         // 262144
#define NTILE 2048              // BB*HH
#define CSP   63

typedef unsigned short ushortt;

// ------------------------------ scratch ------------------------------------
__device__ __align__(16) ushortt g_xh[(size_t)NPX*32];
__device__ __align__(16) ushortt g_xl[(size_t)NPX*32];
__device__ __align__(16) float   g_s1[(size_t)NPX*64];
__device__ __align__(16) ushortt g_y1h[(size_t)NPX*64];
__device__ __align__(16) ushortt g_y1l[(size_t)NPX*64];
__device__ __align__(16) float   g_s2[(size_t)NPX*64];
__device__ __align__(16) float   g_spb[(size_t)NPX*64];
__device__ __align__(16) ushortt g_B1[2*10*64*40];   // padded 80B rows
__device__ __align__(16) ushortt g_B2[2*9*64*64];    // SW128-xor 128B rows
__device__ float g_part[3*NTILE*64*2];
__device__ float g_stats[3*64*2];

// ------------------------------ PTX helpers --------------------------------
__device__ __forceinline__ uint32_t smem_u32(const void* p) {
    uint32_t a;
    asm("{ .reg .u64 t; cvta.to.shared.u64 t, %1; cvt.u32.u64 %0, t; }" : "=r"(a) : "l"(p));
    return a;
}
#define LDSM4(a, addr) \
    asm volatile("ldmatrix.sync.aligned.m8n8.x4.shared.b16 {%0,%1,%2,%3}, [%4];" \
        : "=r"((a)[0]), "=r"((a)[1]), "=r"((a)[2]), "=r"((a)[3]) : "r"(addr))
#define LDSM2(b0, b1, addr) \
    asm volatile("ldmatrix.sync.aligned.m8n8.x2.shared.b16 {%0,%1}, [%2];" \
        : "=r"(b0), "=r"(b1) : "r"(addr))
#define MMA(d, a, b0, b1) \
    asm volatile("mma.sync.aligned.m16n8k16.row.col.f32.bf16.bf16.f32 " \
        "{%0,%1,%2,%3},{%4,%5,%6,%7},{%8,%9},{%0,%1,%2,%3};" \
        : "+f"((d)[0]), "+f"((d)[1]), "+f"((d)[2]), "+f"((d)[3]) \
        : "r"((a)[0]), "r"((a)[1]), "r"((a)[2]), "r"((a)[3]), "r"(b0), "r"(b1))

__device__ __forceinline__ void cpasync16(uint32_t dst, const void* src, bool ok) {
    int sz = ok ? 16 : 0;
    asm volatile("cp.async.cg.shared.global [%0], [%1], 16, %2;"
                 :: "r"(dst), "l"(src), "r"(sz) : "memory");
}
#define CP_COMMIT() asm volatile("cp.async.commit_group;" ::: "memory")
#define CP_WAIT0()  asm volatile("cp.async.wait_group 0;" ::: "memory")
#define CP_WAIT1()  asm volatile("cp.async.wait_group 1;" ::: "memory")

// ---------------------------------------------------------------------------
// Persistent implicit-GEMM conv with mma.sync bf16 (hi/lo 3-pass).
// Tile: M=128 px (one image row) x N=64 oc. 8 warps = 4(M) x 2(N), 32x32 each.
// DUAL: during center tap also accumulate the 1x1 conv (B tap index 9).
// ---------------------------------------------------------------------------
template<int CCH, bool DUAL>
__global__ void __launch_bounds__(256, 1)
convmma_k(const ushortt* __restrict__ Ah_g, const ushortt* __restrict__ Al_g,
          const ushortt* __restrict__ Bimg,
          const float* __restrict__ bias0, const float* __restrict__ bias1,
          float* __restrict__ out0, float* __restrict__ out1,
          float* __restrict__ part0, float* __restrict__ part1)
{
    constexpr int STRIDE = (CCH == 32) ? 80 : 144;   // A row stride (bytes)
    constexpr int KCH    = CCH / 16;
    constexpr int SEGJ   = CCH / 8;                  // 16B segs per px row
    constexpr int AHALF  = 128 * STRIDE;
    constexpr int ABSZ   = 2 * AHALF;
    constexpr int ABUF   = 2560;
    constexpr int BOFF   = ABUF + 2 * ABSZ;
    constexpr int BTAPS  = DUAL ? 10 : 9;
    constexpr int BROWB  = (CCH == 32) ? 80 : 128;   // B row bytes
    constexpr int BTAPSZ = 64 * BROWB;
    constexpr int BHALF  = BTAPS * BTAPSZ;

    extern __shared__ __align__(16) char smem[];
    const uint32_t sb = smem_u32(smem);
    const int t = threadIdx.x, wid = t >> 5, lane = t & 31;

    float* biasm = (float*)smem;                 // [128]
    float* redsm = (float*)(smem + 512);         // [8][32][2]

    if (t < 64)  biasm[t] = (t < CSP) ? bias0[t] : 0.f;
    else if (t < 128) biasm[t] = (DUAL && (t - 64) < CSP) ? bias1[t - 64] : 0.f;

    // resident B image
    {
        const uint4* src = (const uint4*)Bimg;
        uint4* dst = (uint4*)(smem + BOFF);
        const int n16 = 2 * BHALF / 16;
        for (int i = t; i < n16; i += 256) dst[i] = src[i];
    }
    __syncthreads();

    const int mw = wid & 3, nw = wid >> 2;
    const int rid = lane & 7, grp = lane >> 3;
    const int qrow = lane >> 2, qc = lane & 3;
    const int arow = mw*32 + (grp & 1)*8 + rid;
    const int au0  = grp >> 1;
    const int bu0  = grp & 1;

    for (int tile = blockIdx.x; tile < NTILE; tile += gridDim.x) {
        const int b = tile >> 7, y = tile & 127;

        float acc [2][4][4];
        float accp[2][4][4];
#pragma unroll
        for (int mi = 0; mi < 2; mi++)
#pragma unroll
            for (int nf = 0; nf < 4; nf++)
#pragma unroll
                for (int k = 0; k < 4; k++) {
                    acc[mi][nf][k] = 0.f;
                    if (DUAL) accp[mi][nf][k] = 0.f;
                }

        // ---- staging helper (cp.async, zfill at borders) ----
        auto stage_tap = [&](int tap, int buf) {
            const int ky = tap / 3, kx = tap - ky*3;
            const int iy = y + ky - 1;
            const bool rowok = (iy >= 0 && iy < HH);
            const int iyc = rowok ? iy : 0;
            for (int s = t; s < 2*128*SEGJ; s += 256) {
                const int half = s / (128*SEGJ);
                const int r = s - half*(128*SEGJ);
                const int px = r / SEGJ, j = r - px*SEGJ;
                const int ix = px + kx - 1;
                const bool ok = rowok && (ix >= 0) && (ix < WW);
                const int ixc = ok ? ix : 0;
                const ushortt* srcb = half ? Al_g : Ah_g;
                const void* g = (const char*)srcb +
                    (((size_t)((b << 7) + iyc) * 128 + ixc) * CCH + j*8) * 2;
                const uint32_t d = sb + ABUF + buf*ABSZ + half*AHALF + px*STRIDE + j*16;
                cpasync16(d, g, ok);
            }
            CP_COMMIT();
        };

        // ---- compute helper: one tap, 3 passes (hh, hl, lh) ----
        auto compute_tap = [&](int buf, int btap, float (*ac)[4][4]) {
            const uint32_t Ah = sb + ABUF + buf*ABSZ;
            const uint32_t Al = Ah + AHALF;
            auto baddr = [&](int half, int nf, int kc) -> uint32_t {
                const int oc = nw*32 + nf*8 + rid;
                const int u  = kc*2 + bu0;
                if (CCH == 32)
                    return sb + BOFF + half*BHALF + btap*BTAPSZ + oc*80 + u*16;
                else
                    return sb + BOFF + half*BHALF + btap*BTAPSZ + oc*128 + ((u ^ (oc & 7)) * 16);
            };
#pragma unroll
            for (int kc = 0; kc < KCH; kc++) {
                uint32_t a0[4], a1[4];
                LDSM4(a0, Ah + (uint32_t)((arow      )*STRIDE + (au0 + kc*2)*16));
                LDSM4(a1, Ah + (uint32_t)((arow + 16 )*STRIDE + (au0 + kc*2)*16));
#pragma unroll
                for (int hb = 0; hb < 2; hb++)
#pragma unroll
                    for (int nf = 0; nf < 4; nf++) {
                        uint32_t b0, b1;
                        LDSM2(b0, b1, baddr(hb, nf, kc));
                        MMA(ac[0][nf], a0, b0, b1);
                        MMA(ac[1][nf], a1, b0, b1);
                    }
            }
#pragma unroll
            for (int kc = 0; kc < KCH; kc++) {
                uint32_t a0[4], a1[4];
                LDSM4(a0, Al + (uint32_t)((arow      )*STRIDE + (au0 + kc*2)*16));
                LDSM4(a1, Al + (uint32_t)((arow + 16 )*STRIDE + (au0 + kc*2)*16));
#pragma unroll
                for (int nf = 0; nf < 4; nf++) {
                    uint32_t b0, b1;
                    LDSM2(b0, b1, baddr(0, nf, kc));
                    MMA(ac[0][nf], a0, b0, b1);
                    MMA(ac[1][nf], a1, b0, b1);
                }
            }
        };

        // ---- tap pipeline ----
        stage_tap(0, 0);
        for (int tap = 0; tap < 9; tap++) {
            const int buf = tap & 1;
            if (tap < 8) { stage_tap(tap + 1, buf ^ 1); CP_WAIT1(); }
            else         { CP_WAIT0(); }
            __syncthreads();
            compute_tap(buf, tap, acc);
            if (DUAL && tap == 4) compute_tap(buf, 9, accp);
            __syncthreads();
        }

        // ---- epilogue(s) ----
        const int nouts = DUAL ? 2 : 1;
        for (int ba = 0; ba < nouts; ba++) {
            float (*ac)[4][4] = (DUAL && ba) ? accp : acc;
            const float* bsm = biasm + ba*64;
            float* ob = ((DUAL && ba) ? out1 : out0) + (size_t)tile*128*64;
            float* pp = ((DUAL && ba) ? part1 : part0);

#pragma unroll
            for (int nf = 0; nf < 4; nf++) {
                const int c0 = nw*32 + nf*8 + qc*2;
                const float bb0 = bsm[c0], bb1 = bsm[c0 + 1];
                float s0 = 0.f, s1v = 0.f, q0 = 0.f, q1 = 0.f;
#pragma unroll
                for (int mi = 0; mi < 2; mi++)
#pragma unroll
                    for (int rr = 0; rr < 2; rr++) {
                        const int row = mw*32 + mi*16 + rr*8 + qrow;
                        const float v0 = ac[mi][nf][rr*2 + 0] + bb0;
                        const float v1 = ac[mi][nf][rr*2 + 1] + bb1;
                        *(float2*)(ob + (size_t)row*64 + c0) = make_float2(v0, v1);
                        s0 += v0; s1v += v1;
                        q0 = fmaf(v0, v0, q0); q1 = fmaf(v1, v1, q1);
                    }
#pragma unroll
                for (int off = 4; off < 32; off <<= 1) {
                    s0  += __shfl_xor_sync(0xffffffffu, s0,  off);
                    s1v += __shfl_xor_sync(0xffffffffu, s1v, off);
                    q0  += __shfl_xor_sync(0xffffffffu, q0,  off);
                    q1  += __shfl_xor_sync(0xffffffffu, q1,  off);
                }
                if (qrow == 0) {
                    const int lc = nf*8 + qc*2;
                    redsm[(wid*32 + lc)*2 + 0] = s0;
                    redsm[(wid*32 + lc)*2 + 1] = q0;
                    redsm[(wid*32 + lc + 1)*2 + 0] = s1v;
                    redsm[(wid*32 + lc + 1)*2 + 1] = q1;
                }
            }
            __syncthreads();
            if (t < 64) {
                const int nw2 = t >> 5;
                float s = 0.f, q = 0.f;
#pragma unroll
                for (int mw2 = 0; mw2 < 4; mw2++) {
                    const int w2 = nw2*4 + mw2;
                    s += redsm[(w2*32 + (t & 31))*2 + 0];
                    q += redsm[(w2*32 + (t & 31))*2 + 1];
                }
                pp[((size_t)tile*64 + t)*2 + 0] = s;
                pp[((size_t)tile*64 + t)*2 + 1] = q;
            }
            __syncthreads();
        }
    }
}

// ---------------------------------------------------------------------------
// x NCHW fp32 -> NHWC bf16 hi/lo
__global__ __launch_bounds__(256)
void splitx_k(const float* __restrict__ x,
              ushortt* __restrict__ xh, ushortt* __restrict__ xl)
{
    int px = blockIdx.x*256 + threadIdx.x;
    int b = px >> 14, pix = px & (HWSZ - 1);
    const float* xb = x + (size_t)b*32*HWSZ + pix;
    ushortt h[32], l[32];
#pragma unroll
    for (int c = 0; c < 32; c++) {
        float v = xb[(size_t)c*HWSZ];
        __nv_bfloat16 hh = __float2bfloat16(v);
        __nv_bfloat16 ll = __float2bfloat16(v - __bfloat162float(hh));
        h[c] = *(ushortt*)&hh;
        l[c] = *(ushortt*)&ll;
    }
    uint4* dh = (uint4*)(xh + (size_t)px*32);
    uint4* dl = (uint4*)(xl + (size_t)px*32);
#pragma unroll
    for (int i = 0; i < 4; i++) { dh[i] = ((uint4*)h)[i]; dl[i] = ((uint4*)l)[i]; }
}

// weights -> B images in final smem layout (B1 padded 80B rows, B2 SW128-xor)
__global__ __launch_bounds__(256)
void splitw_k(const float* __restrict__ w1, const float* __restrict__ wp,
              const float* __restrict__ w2,
              ushortt* __restrict__ B1, ushortt* __restrict__ B2)
{
    const int i = blockIdx.x*256 + threadIdx.x;
    float val = 0.f; ushortt* dst; int half;
    if (i < 51200) {                                  // B1: [half][10][64][40]
        half = i / 25600;
        int r = i % 25600;
        int tap = r / 2560, r2 = r % 2560, oc = r2 / 40, s = r2 % 40;
        if (s < 32 && oc < CSP) {
            if (tap < 9) { int ky = tap/3, kx = tap%3; val = w1[((oc*32 + s)*3 + ky)*3 + kx]; }
            else         { val = wp[oc*32 + s]; }
        }
        dst = B1 + i;
    } else if (i < 51200 + 73728) {                   // B2: [half][9][64][64]
        int k = i - 51200;
        half = k / 36864;
        int r = k % 36864;
        int tap = r / 4096, r2 = r % 4096, oc = r2 / 64, ps = r2 % 64;
        int u_log = (ps >> 3) ^ (oc & 7);
        int c = u_log*8 + (ps & 7);
        if (oc < CSP) { int ky = tap/3, kx = tap%3; val = w2[((oc*64 + c)*3 + ky)*3 + kx]; }
        dst = B2 + k;
    } else return;
    __nv_bfloat16 hh = __float2bfloat16(val);
    __nv_bfloat16 ll = __float2bfloat16(val - __bfloat162float(hh));
    *dst = half ? *(ushortt*)&ll : *(ushortt*)&hh;
}

// BN finalize over NTILE partials
__global__ __launch_bounds__(256)
void stats_k(const float* __restrict__ part, const float* __restrict__ gamma,
             const float* __restrict__ beta, float* __restrict__ stats)
{
    __shared__ double ss[256], qq[256];
    const int c = blockIdx.x, t = threadIdx.x;
    double s = 0.0, q = 0.0;
    for (int i = 0; i < NTILE/256; i++) {
        const float* p = part + ((size_t)(i*256 + t)*64 + c)*2;
        s += (double)p[0]; q += (double)p[1];
    }
    ss[t] = s; qq[t] = q;
#pragma unroll
    for (int off = 128; off > 0; off >>= 1) {
        __syncthreads();
        if (t < off) { ss[t] += ss[t+off]; qq[t] += qq[t+off]; }
    }
    if (t == 0) {
        const double n = (double)NPX;
        double mu  = ss[0] / n;
        double var = qq[0] / n - mu*mu;
        float rstd = (float)(1.0 / sqrt(var + 1e-5));
        float a  = gamma[c] * rstd;
        float bc = beta[c] - a * (float)mu;
        stats[c*2] = a; stats[c*2+1] = bc;
    }
}

// bn1 + relu + project -> y1 NHWC bf16 hi/lo (ch0 = time)
__global__ __launch_bounds__(256)
void bnrp_k(const float* __restrict__ s1, const float* __restrict__ stats,
            ushortt* __restrict__ yh, ushortt* __restrict__ yl)
{
    __shared__ float a[CSP], bc[CSP];
    int t = threadIdx.x;
    if (t < CSP) { a[t] = stats[2*t]; bc[t] = stats[2*t+1]; }
    __syncthreads();
    size_t px = (size_t)blockIdx.x*256 + t;
    const float* sp = s1 + px*64;
    float q = 0.f;
    ushortt h[64], l[64];
#pragma unroll
    for (int c = 0; c < CSP; c++) {
        float r = fmaxf(fmaf(a[c], sp[c], bc[c]), 0.f);
        q = fmaf(r, r, q);
        __nv_bfloat16 hh = __float2bfloat16(r);
        __nv_bfloat16 ll = __float2bfloat16(r - __bfloat162float(hh));
        h[c+1] = *(ushortt*)&hh; l[c+1] = *(ushortt*)&ll;
    }
    float t0 = sqrtf(1.f + q);
    { __nv_bfloat16 hh = __float2bfloat16(t0);
      __nv_bfloat16 ll = __float2bfloat16(t0 - __bfloat162float(hh));
      h[0] = *(ushortt*)&hh; l[0] = *(ushortt*)&ll; }
    uint4* dh = (uint4*)(yh + px*64);
    uint4* dl = (uint4*)(yl + px*64);
#pragma unroll
    for (int i = 0; i < 8; i++) { dh[i] = ((uint4*)h)[i]; dl[i] = ((uint4*)l)[i]; }
}

// merge + relu + project -> out NCHW fp32
__global__ __launch_bounds__(256)
void final_k(const float* __restrict__ s2, const float* __restrict__ sp,
             const float* __restrict__ st2, const float* __restrict__ stp,
             float* __restrict__ out)
{
    __shared__ float a2[CSP], b2[CSP], ap[CSP], bp[CSP];
    int t = threadIdx.x;
    if (t < CSP) { a2[t] = st2[2*t]; b2[t] = st2[2*t+1]; ap[t] = stp[2*t]; bp[t] = stp[2*t+1]; }
    __syncthreads();
    size_t px = (size_t)blockIdx.x*256 + t;
    int b = (int)(px >> 14), pix = (int)(px & (HWSZ - 1));
    const float* p2 = s2 + px*64;
    const float* pq = sp + px*64;
    float r[CSP]; float q = 0.f;
#pragma unroll
    for (int c = 0; c < CSP; c++) {
        float h = fmaf(a2[c], p2[c], b2[c]) + fmaf(ap[c], pq[c], bp[c]);
        r[c] = fmaxf(h, 0.f);
        q = fmaf(r[c], r[c], q);
    }
    float* ob = out + (size_t)b*64*HWSZ + pix;
    ob[0] = sqrtf(1.f + q);
#pragma unroll
    for (int c = 0; c < CSP; c++) ob[(size_t)(c+1)*HWSZ] = r[c];
}

// ---------------------------------------------------------------------------
extern "C" void kernel_launch(void* const* d_in, const int* in_sizes, int n_in,
                              void* d_out, int out_size)
{
    const float* x   = (const float*)d_in[0];
    const float* w1  = (const float*)d_in[1];
    const float* b1  = (const float*)d_in[2];
    const float* g1  = (const float*)d_in[3];
    const float* bt1 = (const float*)d_in[4];
    const float* w2  = (const float*)d_in[5];
    const float* b2  = (const float*)d_in[6];
    const float* g2  = (const float*)d_in[7];
    const float* bt2 = (const float*)d_in[8];
    const float* wp  = (const float*)d_in[9];
    const float* bp  = (const float*)d_in[10];
    const float* gp  = (const float*)d_in[11];
    const float* btp = (const float*)d_in[12];
    float* out = (float*)d_out;

    void *pxh,*pxl,*ps1,*pyh,*pyl,*ps2,*psp,*pB1,*pB2,*ppart,*pstats;
    cudaGetSymbolAddress(&pxh, g_xh);   cudaGetSymbolAddress(&pxl, g_xl);
    cudaGetSymbolAddress(&ps1, g_s1);   cudaGetSymbolAddress(&pyh, g_y1h);
    cudaGetSymbolAddress(&pyl, g_y1l);  cudaGetSymbolAddress(&ps2, g_s2);
    cudaGetSymbolAddress(&psp, g_spb);  cudaGetSymbolAddress(&pB1, g_B1);
    cudaGetSymbolAddress(&pB2, g_B2);   cudaGetSymbolAddress(&ppart, g_part);
    cudaGetSymbolAddress(&pstats, g_stats);
    ushortt* xh = (ushortt*)pxh;
    ushortt* xl = (ushortt*)pxl;
    float* s1 = (float*)ps1;
    ushortt* yh = (ushortt*)pyh;
    ushortt* yl = (ushortt*)pyl;
    float* s2 = (float*)ps2;
    float* sp = (float*)psp;
    ushortt* B1 = (ushortt*)pB1;
    ushortt* B2 = (ushortt*)pB2;
    float* part  = (float*)ppart;
    float* stats = (float*)pstats;

    // dynamic smem sizes
    const int SM1 = 2560 + 2*(2*128*80)  + 2*(10*64*80);   // 145,920
    const int SM2 = 2560 + 2*(2*128*144) + 2*(9*64*128);   // 223,744
    cudaFuncSetAttribute(convmma_k<32,true>,  cudaFuncAttributeMaxDynamicSharedMemorySize, SM1);
    cudaFuncSetAttribute(convmma_k<64,false>, cudaFuncAttributeMaxDynamicSharedMemorySize, SM2);

    splitx_k<<<NPX/256, 256>>>(x, xh, xl);
    splitw_k<<<489, 256>>>(w1, wp, w2, B1, B2);

    // conv1 (taps 0-8) + convp (tap 9) -> s1, sp + partials
    convmma_k<32,true><<<148, 256, SM1>>>(xh, xl, B1, b1, bp, s1, sp,
                                          part + 0*NTILE*64*2, part + 2*NTILE*64*2);
    stats_k<<<CSP, 256>>>(part + 0*NTILE*64*2, g1, bt1, stats + 0*64*2);
    bnrp_k<<<NPX/256, 256>>>(s1, stats + 0*64*2, yh, yl);

    // conv2 -> s2 + partials
    convmma_k<64,false><<<148, 256, SM2>>>(yh, yl, B2, b2, nullptr, s2, nullptr,
                                           part + 1*NTILE*64*2, nullptr);
    stats_k<<<CSP, 256>>>(part + 1*NTILE*64*2, g2, bt2, stats + 1*64*2);
    stats_k<<<CSP, 256>>>(part + 2*NTILE*64*2, gp, btp, stats + 2*64*2);

    final_k<<<NPX/256, 256>>>(s2, sp, stats + 1*64*2, stats + 2*64*2, out);
}

// round 7
// speedup vs baseline: 2.3808x; 1.2271x over previous
#include <cuda_runtime.h>
#include <cuda_bf16.h>
#include <math.h>
#include <stdint.h>

#define BB    16
#define HH    128
#define WW    128
#define HWSZ  (HH*WW)
#define NPX   (BB*HWSZ)         // 262144
#define NTILE 2048              // BB*HH
#define CSP   63

typedef unsigned short ushortt;

// ------------------------------ scratch ------------------------------------
__device__ __align__(16) ushortt g_xh[(size_t)NPX*32];
__device__ __align__(16) ushortt g_xl[(size_t)NPX*32];
__device__ __align__(16) float   g_s1[(size_t)NPX*64];
__device__ __align__(16) ushortt g_y1h[(size_t)NPX*64];
__device__ __align__(16) ushortt g_y1l[(size_t)NPX*64];
__device__ __align__(16) float   g_s2[(size_t)NPX*64];
__device__ __align__(16) float   g_spb[(size_t)NPX*64];
__device__ __align__(16) ushortt g_B1[2*10*64*40];   // padded 80B rows
__device__ __align__(16) ushortt g_B2[2*9*64*64];    // SW128-xor 128B rows
__device__ float g_part[3*NTILE*64*2];
__device__ float g_stats[3*64*2];

// ------------------------------ PTX helpers --------------------------------
__device__ __forceinline__ uint32_t smem_u32(const void* p) {
    uint32_t a;
    asm("{ .reg .u64 t; cvta.to.shared.u64 t, %1; cvt.u32.u64 %0, t; }" : "=r"(a) : "l"(p));
    return a;
}
#define LDSM4(a, addr) \
    asm volatile("ldmatrix.sync.aligned.m8n8.x4.shared.b16 {%0,%1,%2,%3}, [%4];" \
        : "=r"((a)[0]), "=r"((a)[1]), "=r"((a)[2]), "=r"((a)[3]) : "r"(addr))
#define LDSM2(b0, b1, addr) \
    asm volatile("ldmatrix.sync.aligned.m8n8.x2.shared.b16 {%0,%1}, [%2];" \
        : "=r"(b0), "=r"(b1) : "r"(addr))
#define MMA(d, a, b0, b1) \
    asm volatile("mma.sync.aligned.m16n8k16.row.col.f32.bf16.bf16.f32 " \
        "{%0,%1,%2,%3},{%4,%5,%6,%7},{%8,%9},{%0,%1,%2,%3};" \
        : "+f"((d)[0]), "+f"((d)[1]), "+f"((d)[2]), "+f"((d)[3]) \
        : "r"((a)[0]), "r"((a)[1]), "r"((a)[2]), "r"((a)[3]), "r"(b0), "r"(b1))

__device__ __forceinline__ void cpasync16(uint32_t dst, const void* src, bool ok) {
    int sz = ok ? 16 : 0;
    asm volatile("cp.async.cg.shared.global [%0], [%1], 16, %2;"
                 :: "r"(dst), "l"(src), "r"(sz) : "memory");
}
#define CP_COMMIT() asm volatile("cp.async.commit_group;" ::: "memory")
#define CP_WAIT0()  asm volatile("cp.async.wait_group 0;" ::: "memory")
#define CP_WAIT1()  asm volatile("cp.async.wait_group 1;" ::: "memory")

// ---------------------------------------------------------------------------
// Row-streaming implicit-GEMM conv with mma.sync bf16 (hi/lo 3-pass).
// Each CTA owns a contiguous chunk of output rows in one image. Each input
// row is staged ONCE; it feeds ky=0/1/2 groups of 3 in-flight output rows
// (rotating accumulator sets). kx shifts are smem address offsets.
// DUAL: 1x1 conv (tap 9) on the center row into a separate accumulator.
// ---------------------------------------------------------------------------
template<int CCH, bool DUAL>
__global__ void __launch_bounds__(256, 1)
convmma_k(const ushortt* __restrict__ Ah_g, const ushortt* __restrict__ Al_g,
          const ushortt* __restrict__ Bimg,
          const float* __restrict__ bias0, const float* __restrict__ bias1,
          float* __restrict__ out0, float* __restrict__ out1,
          float* __restrict__ part0, float* __restrict__ part1)
{
    constexpr int STRIDE = (CCH == 32) ? 80 : 144;   // A row stride (bytes)
    constexpr int KCH    = CCH / 16;
    constexpr int SEGJ   = CCH / 8;                  // 16B segs per px row
    constexpr int ROWPX  = 130;                      // px -1..128
    constexpr int AHALF  = ROWPX * STRIDE;
    constexpr int ABSZ   = 2 * AHALF;                // hi + lo
    constexpr int ABUF   = 2560;
    constexpr int BOFF   = ABUF + 2 * ABSZ;
    constexpr int BTAPS  = DUAL ? 10 : 9;
    constexpr int BROWB  = (CCH == 32) ? 80 : 128;
    constexpr int BTAPSZ = 64 * BROWB;
    constexpr int BHALF  = BTAPS * BTAPSZ;

    extern __shared__ __align__(16) char smem[];
    const uint32_t sb = smem_u32(smem);
    const int t = threadIdx.x, wid = t >> 5, lane = t & 31;

    float* biasm = (float*)smem;                 // [128]
    float* redsm = (float*)(smem + 512);         // [8][32][2]

    if (t < 64)  biasm[t] = (t < CSP) ? bias0[t] : 0.f;
    else if (t < 128) biasm[t] = (DUAL && (t - 64) < CSP) ? bias1[t - 64] : 0.f;

    // resident B image
    {
        const uint4* src = (const uint4*)Bimg;
        uint4* dst = (uint4*)(smem + BOFF);
        const int n16 = 2 * BHALF / 16;
        for (int i = t; i < n16; i += 256) dst[i] = src[i];
    }
    __syncthreads();

    const int mw = wid & 3, nw = wid >> 2;
    const int rid = lane & 7, grp = lane >> 3;
    const int qrow = lane >> 2, qc = lane & 3;
    const int arow = mw*32 + (grp & 1)*8 + rid;
    const int au0  = grp >> 1;
    const int bu0  = grp & 1;

    // chunk: image img, output rows [r0y, r0y+len)
    const int img = blockIdx.x / 9;
    const int sub = blockIdx.x % 9;
    const int r0y = sub*14 + (sub < 2 ? sub : 2);
    const int len = 14 + (sub < 2 ? 1 : 0);
    const int yend = r0y + len;

    // ------------- helpers -------------
    auto stage_row = [&](int yy, int buf) {
        const bool rowok = (yy >= 0) && (yy < HH);
        const int yyc = rowok ? yy : 0;
        const size_t rowbase = (size_t)((img << 7) + yyc) * 128 * CCH;
        for (int s = t; s < 2*ROWPX*SEGJ; s += 256) {
            const int half = s / (ROWPX*SEGJ);
            const int r = s - half*(ROWPX*SEGJ);
            const int pxi = r / SEGJ, j = r - pxi*SEGJ;
            const int ix = pxi - 1;
            const bool ok = rowok && (ix >= 0) && (ix < WW);
            const int ixc = ok ? ix : 0;
            const ushortt* srcb = half ? Al_g : Ah_g;
            const void* g = (const void*)(srcb + rowbase + (size_t)ixc*CCH + j*8);
            const uint32_t d = sb + ABUF + (uint32_t)(buf*ABSZ + half*AHALF + pxi*STRIDE + j*16);
            cpasync16(d, g, ok);
        }
        CP_COMMIT();
    };

    auto baddr = [&](int half, int btap, int nf, int kc) -> uint32_t {
        const int oc = nw*32 + nf*8 + rid;
        const int u  = kc*2 + bu0;
        if (CCH == 32)
            return sb + BOFF + (uint32_t)(half*BHALF + btap*BTAPSZ + oc*80 + u*16);
        else
            return sb + BOFF + (uint32_t)(half*BHALF + btap*BTAPSZ + oc*128 + ((u ^ (oc & 7)) * 16));
    };

    auto compute_tap = [&](uint32_t Abase, int btap, float (*ac)[4][4]) {
        const uint32_t Ah = Abase, Al = Abase + AHALF;
#pragma unroll
        for (int kc = 0; kc < KCH; kc++) {
            uint32_t a0[4], a1[4];
            LDSM4(a0, Ah + (uint32_t)((arow      )*STRIDE + (au0 + kc*2)*16));
            LDSM4(a1, Ah + (uint32_t)((arow + 16 )*STRIDE + (au0 + kc*2)*16));
#pragma unroll
            for (int hb = 0; hb < 2; hb++)
#pragma unroll
                for (int nf = 0; nf < 4; nf++) {
                    uint32_t b0, b1;
                    LDSM2(b0, b1, baddr(hb, btap, nf, kc));
                    MMA(ac[0][nf], a0, b0, b1);
                    MMA(ac[1][nf], a1, b0, b1);
                }
        }
#pragma unroll
        for (int kc = 0; kc < KCH; kc++) {
            uint32_t a0[4], a1[4];
            LDSM4(a0, Al + (uint32_t)((arow      )*STRIDE + (au0 + kc*2)*16));
            LDSM4(a1, Al + (uint32_t)((arow + 16 )*STRIDE + (au0 + kc*2)*16));
#pragma unroll
            for (int nf = 0; nf < 4; nf++) {
                uint32_t b0, b1;
                LDSM2(b0, b1, baddr(0, btap, nf, kc));
                MMA(ac[0][nf], a0, b0, b1);
                MMA(ac[1][nf], a1, b0, b1);
            }
        }
    };

    auto compute_group = [&](uint32_t bufbase, int ky, float (*ac)[4][4]) {
#pragma unroll 1
        for (int kx = 0; kx < 3; kx++)
            compute_tap(bufbase + (uint32_t)(kx*STRIDE), ky*3 + kx, ac);
    };

    auto epilogue = [&](float (*ac)[4][4], const float* bsm,
                        float* outT, float* pp, int y) {
        const size_t tile = (size_t)(img*128 + y);
        float* ob = outT + tile*128*64;
#pragma unroll
        for (int nf = 0; nf < 4; nf++) {
            const int c0 = nw*32 + nf*8 + qc*2;
            const float bb0 = bsm[c0], bb1 = bsm[c0 + 1];
            float s0 = 0.f, s1v = 0.f, q0 = 0.f, q1 = 0.f;
#pragma unroll
            for (int mi = 0; mi < 2; mi++)
#pragma unroll
                for (int rr = 0; rr < 2; rr++) {
                    const int row = mw*32 + mi*16 + rr*8 + qrow;
                    const float v0 = ac[mi][nf][rr*2 + 0] + bb0;
                    const float v1 = ac[mi][nf][rr*2 + 1] + bb1;
                    *(float2*)(ob + (size_t)row*64 + c0) = make_float2(v0, v1);
                    s0 += v0; s1v += v1;
                    q0 = fmaf(v0, v0, q0); q1 = fmaf(v1, v1, q1);
                }
#pragma unroll
            for (int off = 4; off < 32; off <<= 1) {
                s0  += __shfl_xor_sync(0xffffffffu, s0,  off);
                s1v += __shfl_xor_sync(0xffffffffu, s1v, off);
                q0  += __shfl_xor_sync(0xffffffffu, q0,  off);
                q1  += __shfl_xor_sync(0xffffffffu, q1,  off);
            }
            if (qrow == 0) {
                const int lc = nf*8 + qc*2;
                redsm[(wid*32 + lc)*2 + 0] = s0;
                redsm[(wid*32 + lc)*2 + 1] = q0;
                redsm[(wid*32 + lc + 1)*2 + 0] = s1v;
                redsm[(wid*32 + lc + 1)*2 + 1] = q1;
            }
        }
        __syncthreads();
        if (t < 64) {
            const int nw2 = t >> 5;
            float s = 0.f, q = 0.f;
#pragma unroll
            for (int mw2 = 0; mw2 < 4; mw2++) {
                const int w2 = nw2*4 + mw2;
                s += redsm[(w2*32 + (t & 31))*2 + 0];
                q += redsm[(w2*32 + (t & 31))*2 + 1];
            }
            pp[(tile*64 + t)*2 + 0] = s;
            pp[(tile*64 + t)*2 + 1] = q;
        }
        __syncthreads();
    };

    // ------------- rotating accumulators -------------
    float accN[2][4][4], accM[2][4][4], accO[2][4][4];
    float accp[2][4][4];

    stage_row(r0y - 1, 0);
    for (int ii = r0y - 1; ii <= yend; ii++) {
        const int buf = (ii - (r0y - 1)) & 1;
        const uint32_t bufbase = sb + ABUF + (uint32_t)(buf*ABSZ);
        if (ii < yend) { stage_row(ii + 1, buf ^ 1); CP_WAIT1(); }
        else           { CP_WAIT0(); }
        __syncthreads();

        if (ii + 1 < yend) {                     // ky=0 for o = ii+1 (init)
#pragma unroll
            for (int mi = 0; mi < 2; mi++)
#pragma unroll
                for (int nf = 0; nf < 4; nf++)
#pragma unroll
                    for (int k = 0; k < 4; k++) accN[mi][nf][k] = 0.f;
            compute_group(bufbase, 0, accN);
        }
        if (ii >= r0y && ii < yend) {            // ky=1 for o = ii
            compute_group(bufbase, 1, accM);
            if (DUAL) {
#pragma unroll
                for (int mi = 0; mi < 2; mi++)
#pragma unroll
                    for (int nf = 0; nf < 4; nf++)
#pragma unroll
                        for (int k = 0; k < 4; k++) accp[mi][nf][k] = 0.f;
                compute_tap(bufbase + STRIDE, 9, accp);
                epilogue(accp, biasm + 64, out1, part1, ii);
            }
        }
        if (ii - 1 >= r0y) {                     // ky=2 for o = ii-1 (final)
            compute_group(bufbase, 2, accO);
            epilogue(accO, biasm, out0, part0, ii - 1);
        }

        // rotate: O <- M <- N
#pragma unroll
        for (int mi = 0; mi < 2; mi++)
#pragma unroll
            for (int nf = 0; nf < 4; nf++)
#pragma unroll
                for (int k = 0; k < 4; k++) {
                    accO[mi][nf][k] = accM[mi][nf][k];
                    accM[mi][nf][k] = accN[mi][nf][k];
                }
        __syncthreads();
    }
}

// ---------------------------------------------------------------------------
// x NCHW fp32 -> NHWC bf16 hi/lo
__global__ __launch_bounds__(256)
void splitx_k(const float* __restrict__ x,
              ushortt* __restrict__ xh, ushortt* __restrict__ xl)
{
    int px = blockIdx.x*256 + threadIdx.x;
    int b = px >> 14, pix = px & (HWSZ - 1);
    const float* xb = x + (size_t)b*32*HWSZ + pix;
    ushortt h[32], l[32];
#pragma unroll
    for (int c = 0; c < 32; c++) {
        float v = xb[(size_t)c*HWSZ];
        __nv_bfloat16 hh = __float2bfloat16(v);
        __nv_bfloat16 ll = __float2bfloat16(v - __bfloat162float(hh));
        h[c] = *(ushortt*)&hh;
        l[c] = *(ushortt*)&ll;
    }
    uint4* dh = (uint4*)(xh + (size_t)px*32);
    uint4* dl = (uint4*)(xl + (size_t)px*32);
#pragma unroll
    for (int i = 0; i < 4; i++) { dh[i] = ((uint4*)h)[i]; dl[i] = ((uint4*)l)[i]; }
}

// weights -> B images in final smem layout (B1 padded 80B rows, B2 SW128-xor)
__global__ __launch_bounds__(256)
void splitw_k(const float* __restrict__ w1, const float* __restrict__ wp,
              const float* __restrict__ w2,
              ushortt* __restrict__ B1, ushortt* __restrict__ B2)
{
    const int i = blockIdx.x*256 + threadIdx.x;
    float val = 0.f; ushortt* dst; int half;
    if (i < 51200) {                                  // B1: [half][10][64][40]
        half = i / 25600;
        int r = i % 25600;
        int tap = r / 2560, r2 = r % 2560, oc = r2 / 40, s = r2 % 40;
        if (s < 32 && oc < CSP) {
            if (tap < 9) { int ky = tap/3, kx = tap%3; val = w1[((oc*32 + s)*3 + ky)*3 + kx]; }
            else         { val = wp[oc*32 + s]; }
        }
        dst = B1 + i;
    } else if (i < 51200 + 73728) {                   // B2: [half][9][64][64]
        int k = i - 51200;
        half = k / 36864;
        int r = k % 36864;
        int tap = r / 4096, r2 = r % 4096, oc = r2 / 64, ps = r2 % 64;
        int u_log = (ps >> 3) ^ (oc & 7);
        int c = u_log*8 + (ps & 7);
        if (oc < CSP) { int ky = tap/3, kx = tap%3; val = w2[((oc*64 + c)*3 + ky)*3 + kx]; }
        dst = B2 + k;
    } else return;
    __nv_bfloat16 hh = __float2bfloat16(val);
    __nv_bfloat16 ll = __float2bfloat16(val - __bfloat162float(hh));
    *dst = half ? *(ushortt*)&ll : *(ushortt*)&hh;
}

// BN finalize — two independent channels per launch (blockIdx.x / 63 selects)
__global__ __launch_bounds__(256)
void stats2_k(const float* __restrict__ partA, const float* __restrict__ gA,
              const float* __restrict__ btA, float* __restrict__ stA,
              const float* __restrict__ partB, const float* __restrict__ gB,
              const float* __restrict__ btB, float* __restrict__ stB)
{
    __shared__ double ss[256], qq[256];
    const bool second = (blockIdx.x >= 63);
    const int c = second ? (blockIdx.x - 63) : blockIdx.x;
    const float* part = second ? partB : partA;
    const float* gamma = second ? gB : gA;
    const float* beta  = second ? btB : btA;
    float* stats = second ? stB : stA;
    const int t = threadIdx.x;
    double s = 0.0, q = 0.0;
    for (int i = 0; i < NTILE/256; i++) {
        const float* p = part + ((size_t)(i*256 + t)*64 + c)*2;
        s += (double)p[0]; q += (double)p[1];
    }
    ss[t] = s; qq[t] = q;
#pragma unroll
    for (int off = 128; off > 0; off >>= 1) {
        __syncthreads();
        if (t < off) { ss[t] += ss[t+off]; qq[t] += qq[t+off]; }
    }
    if (t == 0) {
        const double n = (double)NPX;
        double mu  = ss[0] / n;
        double var = qq[0] / n - mu*mu;
        float rstd = (float)(1.0 / sqrt(var + 1e-5));
        float a  = gamma[c] * rstd;
        float bc = beta[c] - a * (float)mu;
        stats[c*2] = a; stats[c*2+1] = bc;
    }
}

// bn1 + relu + project -> y1 NHWC bf16 hi/lo (ch0 = time)
__global__ __launch_bounds__(256)
void bnrp_k(const float* __restrict__ s1, const float* __restrict__ stats,
            ushortt* __restrict__ yh, ushortt* __restrict__ yl)
{
    __shared__ float a[CSP], bc[CSP];
    int t = threadIdx.x;
    if (t < CSP) { a[t] = stats[2*t]; bc[t] = stats[2*t+1]; }
    __syncthreads();
    size_t px = (size_t)blockIdx.x*256 + t;
    const float* sp = s1 + px*64;
    float q = 0.f;
    ushortt h[64], l[64];
#pragma unroll
    for (int c = 0; c < CSP; c++) {
        float r = fmaxf(fmaf(a[c], sp[c], bc[c]), 0.f);
        q = fmaf(r, r, q);
        __nv_bfloat16 hh = __float2bfloat16(r);
        __nv_bfloat16 ll = __float2bfloat16(r - __bfloat162float(hh));
        h[c+1] = *(ushortt*)&hh; l[c+1] = *(ushortt*)&ll;
    }
    float t0 = sqrtf(1.f + q);
    { __nv_bfloat16 hh = __float2bfloat16(t0);
      __nv_bfloat16 ll = __float2bfloat16(t0 - __bfloat162float(hh));
      h[0] = *(ushortt*)&hh; l[0] = *(ushortt*)&ll; }
    uint4* dh = (uint4*)(yh + px*64);
    uint4* dl = (uint4*)(yl + px*64);
#pragma unroll
    for (int i = 0; i < 8; i++) { dh[i] = ((uint4*)h)[i]; dl[i] = ((uint4*)l)[i]; }
}

// merge + relu + project -> out NCHW fp32
__global__ __launch_bounds__(256)
void final_k(const float* __restrict__ s2, const float* __restrict__ sp,
             const float* __restrict__ st2, const float* __restrict__ stp,
             float* __restrict__ out)
{
    __shared__ float a2[CSP], b2[CSP], ap[CSP], bp[CSP];
    int t = threadIdx.x;
    if (t < CSP) { a2[t] = st2[2*t]; b2[t] = st2[2*t+1]; ap[t] = stp[2*t]; bp[t] = stp[2*t+1]; }
    __syncthreads();
    size_t px = (size_t)blockIdx.x*256 + t;
    int b = (int)(px >> 14), pix = (int)(px & (HWSZ - 1));
    const float* p2 = s2 + px*64;
    const float* pq = sp + px*64;
    float r[CSP]; float q = 0.f;
#pragma unroll
    for (int c = 0; c < CSP; c++) {
        float h = fmaf(a2[c], p2[c], b2[c]) + fmaf(ap[c], pq[c], bp[c]);
        r[c] = fmaxf(h, 0.f);
        q = fmaf(r[c], r[c], q);
    }
    float* ob = out + (size_t)b*64*HWSZ + pix;
    ob[0] = sqrtf(1.f + q);
#pragma unroll
    for (int c = 0; c < CSP; c++) ob[(size_t)(c+1)*HWSZ] = r[c];
}

// ---------------------------------------------------------------------------
extern "C" void kernel_launch(void* const* d_in, const int* in_sizes, int n_in,
                              void* d_out, int out_size)
{
    const float* x   = (const float*)d_in[0];
    const float* w1  = (const float*)d_in[1];
    const float* b1  = (const float*)d_in[2];
    const float* g1  = (const float*)d_in[3];
    const float* bt1 = (const float*)d_in[4];
    const float* w2  = (const float*)d_in[5];
    const float* b2  = (const float*)d_in[6];
    const float* g2  = (const float*)d_in[7];
    const float* bt2 = (const float*)d_in[8];
    const float* wp  = (const float*)d_in[9];
    const float* bp  = (const float*)d_in[10];
    const float* gp  = (const float*)d_in[11];
    const float* btp = (const float*)d_in[12];
    float* out = (float*)d_out;

    void *pxh,*pxl,*ps1,*pyh,*pyl,*ps2,*psp,*pB1,*pB2,*ppart,*pstats;
    cudaGetSymbolAddress(&pxh, g_xh);   cudaGetSymbolAddress(&pxl, g_xl);
    cudaGetSymbolAddress(&ps1, g_s1);   cudaGetSymbolAddress(&pyh, g_y1h);
    cudaGetSymbolAddress(&pyl, g_y1l);  cudaGetSymbolAddress(&ps2, g_s2);
    cudaGetSymbolAddress(&psp, g_spb);  cudaGetSymbolAddress(&pB1, g_B1);
    cudaGetSymbolAddress(&pB2, g_B2);   cudaGetSymbolAddress(&ppart, g_part);
    cudaGetSymbolAddress(&pstats, g_stats);
    ushortt* xh = (ushortt*)pxh;
    ushortt* xl = (ushortt*)pxl;
    float* s1 = (float*)ps1;
    ushortt* yh = (ushortt*)pyh;
    ushortt* yl = (ushortt*)pyl;
    float* s2 = (float*)ps2;
    float* sp = (float*)psp;
    ushortt* B1 = (ushortt*)pB1;
    ushortt* B2 = (ushortt*)pB2;
    float* part  = (float*)ppart;
    float* stats = (float*)pstats;

    // dynamic smem sizes
    const int SM1 = 2560 + 2*(2*130*80)  + 2*(10*64*80);   // 146,560
    const int SM2 = 2560 + 2*(2*130*144) + 2*(9*64*128);   // 224,896
    cudaFuncSetAttribute(convmma_k<32,true>,  cudaFuncAttributeMaxDynamicSharedMemorySize, SM1);
    cudaFuncSetAttribute(convmma_k<64,false>, cudaFuncAttributeMaxDynamicSharedMemorySize, SM2);

    splitx_k<<<NPX/256, 256>>>(x, xh, xl);
    splitw_k<<<489, 256>>>(w1, wp, w2, B1, B2);

    // conv1 (taps 0-8) + convp (tap 9) -> s1, sp + partials
    convmma_k<32,true><<<144, 256, SM1>>>(xh, xl, B1, b1, bp, s1, sp,
                                          part + 0*NTILE*64*2, part + 2*NTILE*64*2);
    stats2_k<<<63, 256>>>(part + 0*NTILE*64*2, g1, bt1, stats + 0*64*2,
                          nullptr, nullptr, nullptr, nullptr);
    bnrp_k<<<NPX/256, 256>>>(s1, stats + 0*64*2, yh, yl);

    // conv2 -> s2 + partials
    convmma_k<64,false><<<144, 256, SM2>>>(yh, yl, B2, b2, nullptr, s2, nullptr,
                                           part + 1*NTILE*64*2, nullptr);
    stats2_k<<<126, 256>>>(part + 1*NTILE*64*2, g2, bt2, stats + 1*64*2,
                           part + 2*NTILE*64*2, gp, btp, stats + 2*64*2);

    final_k<<<NPX/256, 256>>>(s2, sp, stats + 1*64*2, stats + 2*64*2, out);
}

// round 8
// speedup vs baseline: 2.6936x; 1.1314x over previous
#include <cuda_runtime.h>
#include <cuda_fp16.h>
#include <math.h>
#include <stdint.h>

#define BB    16
#define HH    128
#define WW    128
#define HWSZ  (HH*WW)
#define NPX   (BB*HWSZ)         // 262144
#define NTILE 2048              // BB*HH
#define CSP   63

typedef unsigned short ushortt;

// ------------------------------ scratch ------------------------------------
__device__ __align__(16) ushortt g_xh[(size_t)NPX*32];
__device__ __align__(16) ushortt g_xl[(size_t)NPX*32];
__device__ __align__(16) float   g_s1[(size_t)NPX*64];
__device__ __align__(16) ushortt g_y1h[(size_t)NPX*64];
__device__ __align__(16) ushortt g_y1l[(size_t)NPX*64];
__device__ __align__(16) float   g_s2[(size_t)NPX*64];
__device__ __align__(16) float   g_spb[(size_t)NPX*64];
__device__ __align__(16) ushortt g_B1[10*64*40];     // fp16, padded 80B rows
__device__ __align__(16) ushortt g_B2[9*64*64];      // fp16, SW128-xor 128B rows
__device__ float g_part[3*NTILE*64*2];
__device__ float g_stats[3*64*2];

// ------------------------------ PTX helpers --------------------------------
__device__ __forceinline__ uint32_t smem_u32(const void* p) {
    uint32_t a;
    asm("{ .reg .u64 t; cvta.to.shared.u64 t, %1; cvt.u32.u64 %0, t; }" : "=r"(a) : "l"(p));
    return a;
}
#define LDSM4(a, addr) \
    asm volatile("ldmatrix.sync.aligned.m8n8.x4.shared.b16 {%0,%1,%2,%3}, [%4];" \
        : "=r"((a)[0]), "=r"((a)[1]), "=r"((a)[2]), "=r"((a)[3]) : "r"(addr))
#define LDSM2(b0, b1, addr) \
    asm volatile("ldmatrix.sync.aligned.m8n8.x2.shared.b16 {%0,%1}, [%2];" \
        : "=r"(b0), "=r"(b1) : "r"(addr))
#define MMA(d, a, b0, b1) \
    asm volatile("mma.sync.aligned.m16n8k16.row.col.f32.f16.f16.f32 " \
        "{%0,%1,%2,%3},{%4,%5,%6,%7},{%8,%9},{%0,%1,%2,%3};" \
        : "+f"((d)[0]), "+f"((d)[1]), "+f"((d)[2]), "+f"((d)[3]) \
        : "r"((a)[0]), "r"((a)[1]), "r"((a)[2]), "r"((a)[3]), "r"(b0), "r"(b1))

__device__ __forceinline__ void cpasync16(uint32_t dst, const void* src, bool ok) {
    int sz = ok ? 16 : 0;
    asm volatile("cp.async.cg.shared.global [%0], [%1], 16, %2;"
                 :: "r"(dst), "l"(src), "r"(sz) : "memory");
}
#define CP_COMMIT() asm volatile("cp.async.commit_group;" ::: "memory")
#define CP_WAIT0()  asm volatile("cp.async.wait_group 0;" ::: "memory")
#define CP_WAIT1()  asm volatile("cp.async.wait_group 1;" ::: "memory")

// ---------------------------------------------------------------------------
// Row-streaming implicit-GEMM conv, fp16 2-pass (A = hi+lo fp16, B = fp16).
// Each CTA owns a contiguous chunk of output rows in one image. Each input
// row is staged ONCE; feeds ky=0/1/2 groups of 3 in-flight output rows
// (rotating accumulator sets). kx shifts are smem address offsets.
// DUAL: 1x1 conv (tap 9) on the center row into a separate accumulator.
// ---------------------------------------------------------------------------
template<int CCH, bool DUAL>
__global__ void __launch_bounds__(256, 1)
convmma_k(const ushortt* __restrict__ Ah_g, const ushortt* __restrict__ Al_g,
          const ushortt* __restrict__ Bimg,
          const float* __restrict__ bias0, const float* __restrict__ bias1,
          float* __restrict__ out0, float* __restrict__ out1,
          float* __restrict__ part0, float* __restrict__ part1)
{
    constexpr int STRIDE = (CCH == 32) ? 80 : 144;   // A row stride (bytes)
    constexpr int KCH    = CCH / 16;
    constexpr int SEGJ   = CCH / 8;                  // 16B segs per px row
    constexpr int ROWPX  = 130;                      // px -1..128
    constexpr int AHALF  = ROWPX * STRIDE;
    constexpr int ABSZ   = 2 * AHALF;                // hi + lo
    constexpr int ABUF   = 2560;
    constexpr int BOFF   = ABUF + 2 * ABSZ;
    constexpr int BTAPS  = DUAL ? 10 : 9;
    constexpr int BROWB  = (CCH == 32) ? 80 : 128;
    constexpr int BTAPSZ = 64 * BROWB;
    constexpr int BSZTOT = BTAPS * BTAPSZ;

    extern __shared__ __align__(16) char smem[];
    const uint32_t sb = smem_u32(smem);
    const int t = threadIdx.x, wid = t >> 5, lane = t & 31;

    float* biasm = (float*)smem;                 // [128]
    float* redsm = (float*)(smem + 512);         // [8][32][2]

    if (t < 64)  biasm[t] = (t < CSP) ? bias0[t] : 0.f;
    else if (t < 128) biasm[t] = (DUAL && (t - 64) < CSP) ? bias1[t - 64] : 0.f;

    // resident B image
    {
        const uint4* src = (const uint4*)Bimg;
        uint4* dst = (uint4*)(smem + BOFF);
        const int n16 = BSZTOT / 16;
        for (int i = t; i < n16; i += 256) dst[i] = src[i];
    }
    __syncthreads();

    const int mw = wid & 3, nw = wid >> 2;
    const int rid = lane & 7, grp = lane >> 3;
    const int qrow = lane >> 2, qc = lane & 3;
    const int arow = mw*32 + (grp & 1)*8 + rid;
    const int au0  = grp >> 1;
    const int bu0  = grp & 1;

    // chunk: image img, output rows [r0y, r0y+len)
    const int img = blockIdx.x / 9;
    const int sub = blockIdx.x % 9;
    const int r0y = sub*14 + (sub < 2 ? sub : 2);
    const int len = 14 + (sub < 2 ? 1 : 0);
    const int yend = r0y + len;

    // ------------- helpers -------------
    auto stage_row = [&](int yy, int buf) {
        const bool rowok = (yy >= 0) && (yy < HH);
        const int yyc = rowok ? yy : 0;
        const size_t rowbase = (size_t)((img << 7) + yyc) * 128 * CCH;
        for (int s = t; s < 2*ROWPX*SEGJ; s += 256) {
            const int half = s / (ROWPX*SEGJ);
            const int r = s - half*(ROWPX*SEGJ);
            const int pxi = r / SEGJ, j = r - pxi*SEGJ;
            const int ix = pxi - 1;
            const bool ok = rowok && (ix >= 0) && (ix < WW);
            const int ixc = ok ? ix : 0;
            const ushortt* srcb = half ? Al_g : Ah_g;
            const void* g = (const void*)(srcb + rowbase + (size_t)ixc*CCH + j*8);
            const uint32_t d = sb + ABUF + (uint32_t)(buf*ABSZ + half*AHALF + pxi*STRIDE + j*16);
            cpasync16(d, g, ok);
        }
        CP_COMMIT();
    };

    auto baddr = [&](int btap, int nf, int kc) -> uint32_t {
        const int oc = nw*32 + nf*8 + rid;
        const int u  = kc*2 + bu0;
        if (CCH == 32)
            return sb + BOFF + (uint32_t)(btap*BTAPSZ + oc*80 + u*16);
        else
            return sb + BOFF + (uint32_t)(btap*BTAPSZ + oc*128 + ((u ^ (oc & 7)) * 16));
    };

    auto compute_tap = [&](uint32_t Abase, int btap, float (*ac)[4][4]) {
        const uint32_t Ah = Abase, Al = Abase + AHALF;
#pragma unroll
        for (int kc = 0; kc < KCH; kc++) {
            uint32_t ah0[4], ah1[4], al0[4], al1[4];
            const uint32_t aoff = (uint32_t)((au0 + kc*2)*16);
            LDSM4(ah0, Ah + (uint32_t)(arow       *STRIDE) + aoff);
            LDSM4(ah1, Ah + (uint32_t)((arow + 16)*STRIDE) + aoff);
            LDSM4(al0, Al + (uint32_t)(arow       *STRIDE) + aoff);
            LDSM4(al1, Al + (uint32_t)((arow + 16)*STRIDE) + aoff);
#pragma unroll
            for (int nf = 0; nf < 4; nf++) {
                uint32_t b0, b1;
                LDSM2(b0, b1, baddr(btap, nf, kc));
                MMA(ac[0][nf], ah0, b0, b1);
                MMA(ac[1][nf], ah1, b0, b1);
                MMA(ac[0][nf], al0, b0, b1);
                MMA(ac[1][nf], al1, b0, b1);
            }
        }
    };

    auto compute_group = [&](uint32_t bufbase, int ky, float (*ac)[4][4]) {
#pragma unroll 1
        for (int kx = 0; kx < 3; kx++)
            compute_tap(bufbase + (uint32_t)(kx*STRIDE), ky*3 + kx, ac);
    };

    auto epilogue = [&](float (*ac)[4][4], const float* bsm,
                        float* outT, float* pp, int y) {
        const size_t tile = (size_t)(img*128 + y);
        float* ob = outT + tile*128*64;
#pragma unroll
        for (int nf = 0; nf < 4; nf++) {
            const int c0 = nw*32 + nf*8 + qc*2;
            const float bb0 = bsm[c0], bb1 = bsm[c0 + 1];
            float s0 = 0.f, s1v = 0.f, q0 = 0.f, q1 = 0.f;
#pragma unroll
            for (int mi = 0; mi < 2; mi++)
#pragma unroll
                for (int rr = 0; rr < 2; rr++) {
                    const int row = mw*32 + mi*16 + rr*8 + qrow;
                    const float v0 = ac[mi][nf][rr*2 + 0] + bb0;
                    const float v1 = ac[mi][nf][rr*2 + 1] + bb1;
                    *(float2*)(ob + (size_t)row*64 + c0) = make_float2(v0, v1);
                    s0 += v0; s1v += v1;
                    q0 = fmaf(v0, v0, q0); q1 = fmaf(v1, v1, q1);
                }
#pragma unroll
            for (int off = 4; off < 32; off <<= 1) {
                s0  += __shfl_xor_sync(0xffffffffu, s0,  off);
                s1v += __shfl_xor_sync(0xffffffffu, s1v, off);
                q0  += __shfl_xor_sync(0xffffffffu, q0,  off);
                q1  += __shfl_xor_sync(0xffffffffu, q1,  off);
            }
            if (qrow == 0) {
                const int lc = nf*8 + qc*2;
                redsm[(wid*32 + lc)*2 + 0] = s0;
                redsm[(wid*32 + lc)*2 + 1] = q0;
                redsm[(wid*32 + lc + 1)*2 + 0] = s1v;
                redsm[(wid*32 + lc + 1)*2 + 1] = q1;
            }
        }
        __syncthreads();
        if (t < 64) {
            const int nw2 = t >> 5;
            float s = 0.f, q = 0.f;
#pragma unroll
            for (int mw2 = 0; mw2 < 4; mw2++) {
                const int w2 = nw2*4 + mw2;
                s += redsm[(w2*32 + (t & 31))*2 + 0];
                q += redsm[(w2*32 + (t & 31))*2 + 1];
            }
            pp[(tile*64 + t)*2 + 0] = s;
            pp[(tile*64 + t)*2 + 1] = q;
        }
        __syncthreads();
    };

    // ------------- rotating accumulators -------------
    float accN[2][4][4], accM[2][4][4], accO[2][4][4];
    float accp[2][4][4];

    stage_row(r0y - 1, 0);
    for (int ii = r0y - 1; ii <= yend; ii++) {
        const int buf = (ii - (r0y - 1)) & 1;
        const uint32_t bufbase = sb + ABUF + (uint32_t)(buf*ABSZ);
        if (ii < yend) { stage_row(ii + 1, buf ^ 1); CP_WAIT1(); }
        else           { CP_WAIT0(); }
        __syncthreads();

        if (ii + 1 < yend) {                     // ky=0 for o = ii+1 (init)
#pragma unroll
            for (int mi = 0; mi < 2; mi++)
#pragma unroll
                for (int nf = 0; nf < 4; nf++)
#pragma unroll
                    for (int k = 0; k < 4; k++) accN[mi][nf][k] = 0.f;
            compute_group(bufbase, 0, accN);
        }
        if (ii >= r0y && ii < yend) {            // ky=1 for o = ii
            compute_group(bufbase, 1, accM);
            if (DUAL) {
#pragma unroll
                for (int mi = 0; mi < 2; mi++)
#pragma unroll
                    for (int nf = 0; nf < 4; nf++)
#pragma unroll
                        for (int k = 0; k < 4; k++) accp[mi][nf][k] = 0.f;
                compute_tap(bufbase + STRIDE, 9, accp);
                epilogue(accp, biasm + 64, out1, part1, ii);
            }
        }
        if (ii - 1 >= r0y) {                     // ky=2 for o = ii-1 (final)
            compute_group(bufbase, 2, accO);
            epilogue(accO, biasm, out0, part0, ii - 1);
        }

        // rotate: O <- M <- N
#pragma unroll
        for (int mi = 0; mi < 2; mi++)
#pragma unroll
            for (int nf = 0; nf < 4; nf++)
#pragma unroll
                for (int k = 0; k < 4; k++) {
                    accO[mi][nf][k] = accM[mi][nf][k];
                    accM[mi][nf][k] = accN[mi][nf][k];
                }
        __syncthreads();
    }
}

// ---------------------------------------------------------------------------
// x NCHW fp32 -> NHWC fp16 hi/lo
__global__ __launch_bounds__(256)
void splitx_k(const float* __restrict__ x,
              ushortt* __restrict__ xh, ushortt* __restrict__ xl)
{
    int px = blockIdx.x*256 + threadIdx.x;
    int b = px >> 14, pix = px & (HWSZ - 1);
    const float* xb = x + (size_t)b*32*HWSZ + pix;
    ushortt h[32], l[32];
#pragma unroll
    for (int c = 0; c < 32; c++) {
        float v = xb[(size_t)c*HWSZ];
        __half hh = __float2half_rn(v);
        __half ll = __float2half_rn(v - __half2float(hh));
        h[c] = *(ushortt*)&hh;
        l[c] = *(ushortt*)&ll;
    }
    uint4* dh = (uint4*)(xh + (size_t)px*32);
    uint4* dl = (uint4*)(xl + (size_t)px*32);
#pragma unroll
    for (int i = 0; i < 4; i++) { dh[i] = ((uint4*)h)[i]; dl[i] = ((uint4*)l)[i]; }
}

// weights -> fp16 B images (B1 padded 80B rows, B2 SW128-xor)
__global__ __launch_bounds__(256)
void splitw_k(const float* __restrict__ w1, const float* __restrict__ wp,
              const float* __restrict__ w2,
              ushortt* __restrict__ B1, ushortt* __restrict__ B2)
{
    const int i = blockIdx.x*256 + threadIdx.x;
    float val = 0.f; ushortt* dst;
    if (i < 25600) {                                  // B1: [10][64][40]
        int tap = i / 2560, r2 = i % 2560, oc = r2 / 40, s = r2 % 40;
        if (s < 32 && oc < CSP) {
            if (tap < 9) { int ky = tap/3, kx = tap%3; val = w1[((oc*32 + s)*3 + ky)*3 + kx]; }
            else         { val = wp[oc*32 + s]; }
        }
        dst = B1 + i;
    } else if (i < 25600 + 36864) {                   // B2: [9][64][64]
        int k = i - 25600;
        int tap = k / 4096, r2 = k % 4096, oc = r2 / 64, ps = r2 % 64;
        int u_log = (ps >> 3) ^ (oc & 7);
        int c = u_log*8 + (ps & 7);
        if (oc < CSP) { int ky = tap/3, kx = tap%3; val = w2[((oc*64 + c)*3 + ky)*3 + kx]; }
        dst = B2 + k;
    } else return;
    __half hv = __float2half_rn(val);
    *dst = *(ushortt*)&hv;
}

// BN finalize — two independent stats per launch (blockIdx.x / 63 selects)
__global__ __launch_bounds__(256)
void stats2_k(const float* __restrict__ partA, const float* __restrict__ gA,
              const float* __restrict__ btA, float* __restrict__ stA,
              const float* __restrict__ partB, const float* __restrict__ gB,
              const float* __restrict__ btB, float* __restrict__ stB)
{
    __shared__ double ss[256], qq[256];
    const bool second = (blockIdx.x >= 63);
    const int c = second ? (blockIdx.x - 63) : blockIdx.x;
    const float* part = second ? partB : partA;
    const float* gamma = second ? gB : gA;
    const float* beta  = second ? btB : btA;
    float* stats = second ? stB : stA;
    const int t = threadIdx.x;
    double s = 0.0, q = 0.0;
    for (int i = 0; i < NTILE/256; i++) {
        const float* p = part + ((size_t)(i*256 + t)*64 + c)*2;
        s += (double)p[0]; q += (double)p[1];
    }
    ss[t] = s; qq[t] = q;
#pragma unroll
    for (int off = 128; off > 0; off >>= 1) {
        __syncthreads();
        if (t < off) { ss[t] += ss[t+off]; qq[t] += qq[t+off]; }
    }
    if (t == 0) {
        const double n = (double)NPX;
        double mu  = ss[0] / n;
        double var = qq[0] / n - mu*mu;
        float rstd = (float)(1.0 / sqrt(var + 1e-5));
        float a  = gamma[c] * rstd;
        float bc = beta[c] - a * (float)mu;
        stats[c*2] = a; stats[c*2+1] = bc;
    }
}

// bn1 + relu + project -> y1 NHWC fp16 hi/lo (ch0 = time)
__global__ __launch_bounds__(256)
void bnrp_k(const float* __restrict__ s1, const float* __restrict__ stats,
            ushortt* __restrict__ yh, ushortt* __restrict__ yl)
{
    __shared__ float a[CSP], bc[CSP];
    int t = threadIdx.x;
    if (t < CSP) { a[t] = stats[2*t]; bc[t] = stats[2*t+1]; }
    __syncthreads();
    size_t px = (size_t)blockIdx.x*256 + t;
    const float* sp = s1 + px*64;
    float q = 0.f;
    ushortt h[64], l[64];
#pragma unroll
    for (int c = 0; c < CSP; c++) {
        float r = fmaxf(fmaf(a[c], sp[c], bc[c]), 0.f);
        q = fmaf(r, r, q);
        __half hh = __float2half_rn(r);
        __half ll = __float2half_rn(r - __half2float(hh));
        h[c+1] = *(ushortt*)&hh; l[c+1] = *(ushortt*)&ll;
    }
    float t0 = sqrtf(1.f + q);
    { __half hh = __float2half_rn(t0);
      __half ll = __float2half_rn(t0 - __half2float(hh));
      h[0] = *(ushortt*)&hh; l[0] = *(ushortt*)&ll; }
    uint4* dh = (uint4*)(yh + px*64);
    uint4* dl = (uint4*)(yl + px*64);
#pragma unroll
    for (int i = 0; i < 8; i++) { dh[i] = ((uint4*)h)[i]; dl[i] = ((uint4*)l)[i]; }
}

// merge + relu + project -> out NCHW fp32
__global__ __launch_bounds__(256)
void final_k(const float* __restrict__ s2, const float* __restrict__ sp,
             const float* __restrict__ st2, const float* __restrict__ stp,
             float* __restrict__ out)
{
    __shared__ float a2[CSP], b2[CSP], ap[CSP], bp[CSP];
    int t = threadIdx.x;
    if (t < CSP) { a2[t] = st2[2*t]; b2[t] = st2[2*t+1]; ap[t] = stp[2*t]; bp[t] = stp[2*t+1]; }
    __syncthreads();
    size_t px = (size_t)blockIdx.x*256 + t;
    int b = (int)(px >> 14), pix = (int)(px & (HWSZ - 1));
    const float* p2 = s2 + px*64;
    const float* pq = sp + px*64;
    float r[CSP]; float q = 0.f;
#pragma unroll
    for (int c = 0; c < CSP; c++) {
        float h = fmaf(a2[c], p2[c], b2[c]) + fmaf(ap[c], pq[c], bp[c]);
        r[c] = fmaxf(h, 0.f);
        q = fmaf(r[c], r[c], q);
    }
    float* ob = out + (size_t)b*64*HWSZ + pix;
    ob[0] = sqrtf(1.f + q);
#pragma unroll
    for (int c = 0; c < CSP; c++) ob[(size_t)(c+1)*HWSZ] = r[c];
}

// ---------------------------------------------------------------------------
extern "C" void kernel_launch(void* const* d_in, const int* in_sizes, int n_in,
                              void* d_out, int out_size)
{
    const float* x   = (const float*)d_in[0];
    const float* w1  = (const float*)d_in[1];
    const float* b1  = (const float*)d_in[2];
    const float* g1  = (const float*)d_in[3];
    const float* bt1 = (const float*)d_in[4];
    const float* w2  = (const float*)d_in[5];
    const float* b2  = (const float*)d_in[6];
    const float* g2  = (const float*)d_in[7];
    const float* bt2 = (const float*)d_in[8];
    const float* wp  = (const float*)d_in[9];
    const float* bp  = (const float*)d_in[10];
    const float* gp  = (const float*)d_in[11];
    const float* btp = (const float*)d_in[12];
    float* out = (float*)d_out;

    void *pxh,*pxl,*ps1,*pyh,*pyl,*ps2,*psp,*pB1,*pB2,*ppart,*pstats;
    cudaGetSymbolAddress(&pxh, g_xh);   cudaGetSymbolAddress(&pxl, g_xl);
    cudaGetSymbolAddress(&ps1, g_s1);   cudaGetSymbolAddress(&pyh, g_y1h);
    cudaGetSymbolAddress(&pyl, g_y1l);  cudaGetSymbolAddress(&ps2, g_s2);
    cudaGetSymbolAddress(&psp, g_spb);  cudaGetSymbolAddress(&pB1, g_B1);
    cudaGetSymbolAddress(&pB2, g_B2);   cudaGetSymbolAddress(&ppart, g_part);
    cudaGetSymbolAddress(&pstats, g_stats);
    ushortt* xh = (ushortt*)pxh;
    ushortt* xl = (ushortt*)pxl;
    float* s1 = (float*)ps1;
    ushortt* yh = (ushortt*)pyh;
    ushortt* yl = (ushortt*)pyl;
    float* s2 = (float*)ps2;
    float* sp = (float*)psp;
    ushortt* B1 = (ushortt*)pB1;
    ushortt* B2 = (ushortt*)pB2;
    float* part  = (float*)ppart;
    float* stats = (float*)pstats;

    // dynamic smem sizes
    const int SM1 = 2560 + 2*(2*130*80)  + 10*64*80;   // 95,360
    const int SM2 = 2560 + 2*(2*130*144) + 9*64*128;   // 151,168
    cudaFuncSetAttribute(convmma_k<32,true>,  cudaFuncAttributeMaxDynamicSharedMemorySize, SM1);
    cudaFuncSetAttribute(convmma_k<64,false>, cudaFuncAttributeMaxDynamicSharedMemorySize, SM2);

    splitx_k<<<NPX/256, 256>>>(x, xh, xl);
    splitw_k<<<245, 256>>>(w1, wp, w2, B1, B2);

    // conv1 (taps 0-8) + convp (tap 9) -> s1, sp + partials
    convmma_k<32,true><<<144, 256, SM1>>>(xh, xl, B1, b1, bp, s1, sp,
                                          part + 0*NTILE*64*2, part + 2*NTILE*64*2);
    stats2_k<<<63, 256>>>(part + 0*NTILE*64*2, g1, bt1, stats + 0*64*2,
                          nullptr, nullptr, nullptr, nullptr);
    bnrp_k<<<NPX/256, 256>>>(s1, stats + 0*64*2, yh, yl);

    // conv2 -> s2 + partials
    convmma_k<64,false><<<144, 256, SM2>>>(yh, yl, B2, b2, nullptr, s2, nullptr,
                                           part + 1*NTILE*64*2, nullptr);
    stats2_k<<<126, 256>>>(part + 1*NTILE*64*2, g2, bt2, stats + 1*64*2,
                           part + 2*NTILE*64*2, gp, btp, stats + 2*64*2);

    final_k<<<NPX/256, 256>>>(s2, sp, stats + 1*64*2, stats + 2*64*2, out);
}

// round 9
// speedup vs baseline: 3.1319x; 1.1627x over previous
#include <cuda_runtime.h>
#include <cuda_fp16.h>
#include <math.h>
#include <stdint.h>

#define BB    16
#define HH    128
#define WW    128
#define HWSZ  (HH*WW)
#define NPX   (BB*HWSZ)         // 262144
#define NTILE 2048              // BB*HH
#define CSP   63

typedef unsigned short ushortt;

// ------------------------------ scratch ------------------------------------
__device__ __align__(16) ushortt g_xh[(size_t)NPX*32];
__device__ __align__(16) float   g_s1[(size_t)NPX*64];
__device__ __align__(16) ushortt g_y1h[(size_t)NPX*64];
__device__ __align__(16) float   g_s2[(size_t)NPX*64];
__device__ __align__(16) float   g_spb[(size_t)NPX*64];
__device__ __align__(16) ushortt g_B1[10*64*40];     // fp16, padded 80B rows
__device__ __align__(16) ushortt g_B2[9*64*64];      // fp16, SW128-xor 128B rows
__device__ float g_part[3*NTILE*64*2];
__device__ float g_stats[3*64*2];

// ------------------------------ PTX helpers --------------------------------
__device__ __forceinline__ uint32_t smem_u32(const void* p) {
    uint32_t a;
    asm("{ .reg .u64 t; cvta.to.shared.u64 t, %1; cvt.u32.u64 %0, t; }" : "=r"(a) : "l"(p));
    return a;
}
#define LDSM4(a, addr) \
    asm volatile("ldmatrix.sync.aligned.m8n8.x4.shared.b16 {%0,%1,%2,%3}, [%4];" \
        : "=r"((a)[0]), "=r"((a)[1]), "=r"((a)[2]), "=r"((a)[3]) : "r"(addr))
#define LDSM2(b0, b1, addr) \
    asm volatile("ldmatrix.sync.aligned.m8n8.x2.shared.b16 {%0,%1}, [%2];" \
        : "=r"(b0), "=r"(b1) : "r"(addr))
#define MMA(d, a, b0, b1) \
    asm volatile("mma.sync.aligned.m16n8k16.row.col.f32.f16.f16.f32 " \
        "{%0,%1,%2,%3},{%4,%5,%6,%7},{%8,%9},{%0,%1,%2,%3};" \
        : "+f"((d)[0]), "+f"((d)[1]), "+f"((d)[2]), "+f"((d)[3]) \
        : "r"((a)[0]), "r"((a)[1]), "r"((a)[2]), "r"((a)[3]), "r"(b0), "r"(b1))

__device__ __forceinline__ void cpasync16(uint32_t dst, const void* src, bool ok) {
    int sz = ok ? 16 : 0;
    asm volatile("cp.async.cg.shared.global [%0], [%1], 16, %2;"
                 :: "r"(dst), "l"(src), "r"(sz) : "memory");
}
#define CP_COMMIT() asm volatile("cp.async.commit_group;" ::: "memory")
#define CP_WAIT0()  asm volatile("cp.async.wait_group 0;" ::: "memory")
#define CP_WAIT1()  asm volatile("cp.async.wait_group 1;" ::: "memory")

// ---------------------------------------------------------------------------
// Row-streaming implicit-GEMM conv, fp16 single-pass (A fp16, B fp16).
// Each CTA owns a contiguous chunk of output rows in one image. Each input
// row is staged ONCE; feeds ky=0/1/2 groups of 3 in-flight output rows
// (rotating accumulator sets). kx shifts are smem address offsets.
// DUAL: 1x1 conv (tap 9) on the center row into a separate accumulator.
// ---------------------------------------------------------------------------
template<int CCH, bool DUAL>
__global__ void __launch_bounds__(256, 1)
convmma_k(const ushortt* __restrict__ Ah_g,
          const ushortt* __restrict__ Bimg,
          const float* __restrict__ bias0, const float* __restrict__ bias1,
          float* __restrict__ out0, float* __restrict__ out1,
          float* __restrict__ part0, float* __restrict__ part1)
{
    constexpr int STRIDE = (CCH == 32) ? 80 : 144;   // A row stride (bytes)
    constexpr int KCH    = CCH / 16;
    constexpr int SEGJ   = CCH / 8;                  // 16B segs per px row
    constexpr int ROWPX  = 130;                      // px -1..128
    constexpr int ABSZ   = ROWPX * STRIDE;
    constexpr int ABUF   = 2560;
    constexpr int BOFF   = ABUF + 2 * ABSZ;
    constexpr int BTAPS  = DUAL ? 10 : 9;
    constexpr int BROWB  = (CCH == 32) ? 80 : 128;
    constexpr int BTAPSZ = 64 * BROWB;
    constexpr int BSZTOT = BTAPS * BTAPSZ;

    extern __shared__ __align__(16) char smem[];
    const uint32_t sb = smem_u32(smem);
    const int t = threadIdx.x, wid = t >> 5, lane = t & 31;

    float* biasm = (float*)smem;                 // [128]
    float* redsm = (float*)(smem + 512);         // [8][32][2]

    if (t < 64)  biasm[t] = (t < CSP) ? bias0[t] : 0.f;
    else if (t < 128) biasm[t] = (DUAL && (t - 64) < CSP) ? bias1[t - 64] : 0.f;

    // resident B image
    {
        const uint4* src = (const uint4*)Bimg;
        uint4* dst = (uint4*)(smem + BOFF);
        const int n16 = BSZTOT / 16;
        for (int i = t; i < n16; i += 256) dst[i] = src[i];
    }
    __syncthreads();

    const int mw = wid & 3, nw = wid >> 2;
    const int rid = lane & 7, grp = lane >> 3;
    const int qrow = lane >> 2, qc = lane & 3;
    const int arow = mw*32 + (grp & 1)*8 + rid;
    const int au0  = grp >> 1;
    const int bu0  = grp & 1;

    // chunk: image img, output rows [r0y, r0y+len)
    const int img = blockIdx.x / 9;
    const int sub = blockIdx.x % 9;
    const int r0y = sub*14 + (sub < 2 ? sub : 2);
    const int len = 14 + (sub < 2 ? 1 : 0);
    const int yend = r0y + len;

    // ------------- helpers -------------
    auto stage_row = [&](int yy, int buf) {
        const bool rowok = (yy >= 0) && (yy < HH);
        const int yyc = rowok ? yy : 0;
        const size_t rowbase = (size_t)((img << 7) + yyc) * 128 * CCH;
        for (int s = t; s < ROWPX*SEGJ; s += 256) {
            const int pxi = s / SEGJ, j = s - pxi*SEGJ;
            const int ix = pxi - 1;
            const bool ok = rowok && (ix >= 0) && (ix < WW);
            const int ixc = ok ? ix : 0;
            const void* g = (const void*)(Ah_g + rowbase + (size_t)ixc*CCH + j*8);
            const uint32_t d = sb + ABUF + (uint32_t)(buf*ABSZ + pxi*STRIDE + j*16);
            cpasync16(d, g, ok);
        }
        CP_COMMIT();
    };

    auto baddr = [&](int btap, int nf, int kc) -> uint32_t {
        const int oc = nw*32 + nf*8 + rid;
        const int u  = kc*2 + bu0;
        if (CCH == 32)
            return sb + BOFF + (uint32_t)(btap*BTAPSZ + oc*80 + u*16);
        else
            return sb + BOFF + (uint32_t)(btap*BTAPSZ + oc*128 + ((u ^ (oc & 7)) * 16));
    };

    auto compute_tap = [&](uint32_t Abase, int btap, float (*ac)[4][4]) {
#pragma unroll
        for (int kc = 0; kc < KCH; kc++) {
            uint32_t a0[4], a1[4];
            const uint32_t aoff = (uint32_t)((au0 + kc*2)*16);
            LDSM4(a0, Abase + (uint32_t)(arow       *STRIDE) + aoff);
            LDSM4(a1, Abase + (uint32_t)((arow + 16)*STRIDE) + aoff);
#pragma unroll
            for (int nf = 0; nf < 4; nf++) {
                uint32_t b0, b1;
                LDSM2(b0, b1, baddr(btap, nf, kc));
                MMA(ac[0][nf], a0, b0, b1);
                MMA(ac[1][nf], a1, b0, b1);
            }
        }
    };

    auto compute_group = [&](uint32_t bufbase, int ky, float (*ac)[4][4]) {
#pragma unroll 1
        for (int kx = 0; kx < 3; kx++)
            compute_tap(bufbase + (uint32_t)(kx*STRIDE), ky*3 + kx, ac);
    };

    auto epilogue = [&](float (*ac)[4][4], const float* bsm,
                        float* outT, float* pp, int y) {
        const size_t tile = (size_t)(img*128 + y);
        float* ob = outT + tile*128*64;
#pragma unroll
        for (int nf = 0; nf < 4; nf++) {
            const int c0 = nw*32 + nf*8 + qc*2;
            const float bb0 = bsm[c0], bb1 = bsm[c0 + 1];
            float s0 = 0.f, s1v = 0.f, q0 = 0.f, q1 = 0.f;
#pragma unroll
            for (int mi = 0; mi < 2; mi++)
#pragma unroll
                for (int rr = 0; rr < 2; rr++) {
                    const int row = mw*32 + mi*16 + rr*8 + qrow;
                    const float v0 = ac[mi][nf][rr*2 + 0] + bb0;
                    const float v1 = ac[mi][nf][rr*2 + 1] + bb1;
                    *(float2*)(ob + (size_t)row*64 + c0) = make_float2(v0, v1);
                    s0 += v0; s1v += v1;
                    q0 = fmaf(v0, v0, q0); q1 = fmaf(v1, v1, q1);
                }
#pragma unroll
            for (int off = 4; off < 32; off <<= 1) {
                s0  += __shfl_xor_sync(0xffffffffu, s0,  off);
                s1v += __shfl_xor_sync(0xffffffffu, s1v, off);
                q0  += __shfl_xor_sync(0xffffffffu, q0,  off);
                q1  += __shfl_xor_sync(0xffffffffu, q1,  off);
            }
            if (qrow == 0) {
                const int lc = nf*8 + qc*2;
                redsm[(wid*32 + lc)*2 + 0] = s0;
                redsm[(wid*32 + lc)*2 + 1] = q0;
                redsm[(wid*32 + lc + 1)*2 + 0] = s1v;
                redsm[(wid*32 + lc + 1)*2 + 1] = q1;
            }
        }
        __syncthreads();
        if (t < 64) {
            const int nw2 = t >> 5;
            float s = 0.f, q = 0.f;
#pragma unroll
            for (int mw2 = 0; mw2 < 4; mw2++) {
                const int w2 = nw2*4 + mw2;
                s += redsm[(w2*32 + (t & 31))*2 + 0];
                q += redsm[(w2*32 + (t & 31))*2 + 1];
            }
            pp[(tile*64 + t)*2 + 0] = s;
            pp[(tile*64 + t)*2 + 1] = q;
        }
        __syncthreads();
    };

    // ------------- rotating accumulators -------------
    float accN[2][4][4], accM[2][4][4], accO[2][4][4];
    float accp[2][4][4];

    stage_row(r0y - 1, 0);
    for (int ii = r0y - 1; ii <= yend; ii++) {
        const int buf = (ii - (r0y - 1)) & 1;
        const uint32_t bufbase = sb + ABUF + (uint32_t)(buf*ABSZ);
        if (ii < yend) { stage_row(ii + 1, buf ^ 1); CP_WAIT1(); }
        else           { CP_WAIT0(); }
        __syncthreads();

        if (ii + 1 < yend) {                     // ky=0 for o = ii+1 (init)
#pragma unroll
            for (int mi = 0; mi < 2; mi++)
#pragma unroll
                for (int nf = 0; nf < 4; nf++)
#pragma unroll
                    for (int k = 0; k < 4; k++) accN[mi][nf][k] = 0.f;
            compute_group(bufbase, 0, accN);
        }
        if (ii >= r0y && ii < yend) {            // ky=1 for o = ii
            compute_group(bufbase, 1, accM);
            if (DUAL) {
#pragma unroll
                for (int mi = 0; mi < 2; mi++)
#pragma unroll
                    for (int nf = 0; nf < 4; nf++)
#pragma unroll
                        for (int k = 0; k < 4; k++) accp[mi][nf][k] = 0.f;
                compute_tap(bufbase + STRIDE, 9, accp);
                epilogue(accp, biasm + 64, out1, part1, ii);
            }
        }
        if (ii - 1 >= r0y) {                     // ky=2 for o = ii-1 (final)
            compute_group(bufbase, 2, accO);
            epilogue(accO, biasm, out0, part0, ii - 1);
        }

        // rotate: O <- M <- N
#pragma unroll
        for (int mi = 0; mi < 2; mi++)
#pragma unroll
            for (int nf = 0; nf < 4; nf++)
#pragma unroll
                for (int k = 0; k < 4; k++) {
                    accO[mi][nf][k] = accM[mi][nf][k];
                    accM[mi][nf][k] = accN[mi][nf][k];
                }
        __syncthreads();
    }
}

// ---------------------------------------------------------------------------
// x NCHW fp32 -> NHWC fp16
__global__ __launch_bounds__(256)
void splitx_k(const float* __restrict__ x, ushortt* __restrict__ xh)
{
    int px = blockIdx.x*256 + threadIdx.x;
    int b = px >> 14, pix = px & (HWSZ - 1);
    const float* xb = x + (size_t)b*32*HWSZ + pix;
    ushortt h[32];
#pragma unroll
    for (int c = 0; c < 32; c++) {
        __half hh = __float2half_rn(xb[(size_t)c*HWSZ]);
        h[c] = *(ushortt*)&hh;
    }
    uint4* dh = (uint4*)(xh + (size_t)px*32);
#pragma unroll
    for (int i = 0; i < 4; i++) dh[i] = ((uint4*)h)[i];
}

// weights -> fp16 B images (B1 padded 80B rows, B2 SW128-xor)
__global__ __launch_bounds__(256)
void splitw_k(const float* __restrict__ w1, const float* __restrict__ wp,
              const float* __restrict__ w2,
              ushortt* __restrict__ B1, ushortt* __restrict__ B2)
{
    const int i = blockIdx.x*256 + threadIdx.x;
    float val = 0.f; ushortt* dst;
    if (i < 25600) {                                  // B1: [10][64][40]
        int tap = i / 2560, r2 = i % 2560, oc = r2 / 40, s = r2 % 40;
        if (s < 32 && oc < CSP) {
            if (tap < 9) { int ky = tap/3, kx = tap%3; val = w1[((oc*32 + s)*3 + ky)*3 + kx]; }
            else         { val = wp[oc*32 + s]; }
        }
        dst = B1 + i;
    } else if (i < 25600 + 36864) {                   // B2: [9][64][64]
        int k = i - 25600;
        int tap = k / 4096, r2 = k % 4096, oc = r2 / 64, ps = r2 % 64;
        int u_log = (ps >> 3) ^ (oc & 7);
        int c = u_log*8 + (ps & 7);
        if (oc < CSP) { int ky = tap/3, kx = tap%3; val = w2[((oc*64 + c)*3 + ky)*3 + kx]; }
        dst = B2 + k;
    } else return;
    __half hv = __float2half_rn(val);
    *dst = *(ushortt*)&hv;
}

// BN finalize — two independent stats per launch (blockIdx.x / 63 selects)
__global__ __launch_bounds__(256)
void stats2_k(const float* __restrict__ partA, const float* __restrict__ gA,
              const float* __restrict__ btA, float* __restrict__ stA,
              const float* __restrict__ partB, const float* __restrict__ gB,
              const float* __restrict__ btB, float* __restrict__ stB)
{
    __shared__ double ss[256], qq[256];
    const bool second = (blockIdx.x >= 63);
    const int c = second ? (blockIdx.x - 63) : blockIdx.x;
    const float* part = second ? partB : partA;
    const float* gamma = second ? gB : gA;
    const float* beta  = second ? btB : btA;
    float* stats = second ? stB : stA;
    const int t = threadIdx.x;
    double s = 0.0, q = 0.0;
    for (int i = 0; i < NTILE/256; i++) {
        const float* p = part + ((size_t)(i*256 + t)*64 + c)*2;
        s += (double)p[0]; q += (double)p[1];
    }
    ss[t] = s; qq[t] = q;
#pragma unroll
    for (int off = 128; off > 0; off >>= 1) {
        __syncthreads();
        if (t < off) { ss[t] += ss[t+off]; qq[t] += qq[t+off]; }
    }
    if (t == 0) {
        const double n = (double)NPX;
        double mu  = ss[0] / n;
        double var = qq[0] / n - mu*mu;
        float rstd = (float)(1.0 / sqrt(var + 1e-5));
        float a  = gamma[c] * rstd;
        float bc = beta[c] - a * (float)mu;
        stats[c*2] = a; stats[c*2+1] = bc;
    }
}

// bn1 + relu + project -> y1 NHWC fp16 (ch0 = time)
__global__ __launch_bounds__(256)
void bnrp_k(const float* __restrict__ s1, const float* __restrict__ stats,
            ushortt* __restrict__ yh)
{
    __shared__ float a[CSP], bc[CSP];
    int t = threadIdx.x;
    if (t < CSP) { a[t] = stats[2*t]; bc[t] = stats[2*t+1]; }
    __syncthreads();
    size_t px = (size_t)blockIdx.x*256 + t;
    const float* sp = s1 + px*64;
    float q = 0.f;
    ushortt h[64];
#pragma unroll
    for (int c = 0; c < CSP; c++) {
        float r = fmaxf(fmaf(a[c], sp[c], bc[c]), 0.f);
        q = fmaf(r, r, q);
        __half hh = __float2half_rn(r);
        h[c+1] = *(ushortt*)&hh;
    }
    float t0 = sqrtf(1.f + q);
    { __half hh = __float2half_rn(t0); h[0] = *(ushortt*)&hh; }
    uint4* dh = (uint4*)(yh + px*64);
#pragma unroll
    for (int i = 0; i < 8; i++) dh[i] = ((uint4*)h)[i];
}

// merge + relu + project -> out NCHW fp32
__global__ __launch_bounds__(256)
void final_k(const float* __restrict__ s2, const float* __restrict__ sp,
             const float* __restrict__ st2, const float* __restrict__ stp,
             float* __restrict__ out)
{
    __shared__ float a2[CSP], b2[CSP], ap[CSP], bp[CSP];
    int t = threadIdx.x;
    if (t < CSP) { a2[t] = st2[2*t]; b2[t] = st2[2*t+1]; ap[t] = stp[2*t]; bp[t] = stp[2*t+1]; }
    __syncthreads();
    size_t px = (size_t)blockIdx.x*256 + t;
    int b = (int)(px >> 14), pix = (int)(px & (HWSZ - 1));
    const float* p2 = s2 + px*64;
    const float* pq = sp + px*64;
    float r[CSP]; float q = 0.f;
#pragma unroll
    for (int c = 0; c < CSP; c++) {
        float h = fmaf(a2[c], p2[c], b2[c]) + fmaf(ap[c], pq[c], bp[c]);
        r[c] = fmaxf(h, 0.f);
        q = fmaf(r[c], r[c], q);
    }
    float* ob = out + (size_t)b*64*HWSZ + pix;
    ob[0] = sqrtf(1.f + q);
#pragma unroll
    for (int c = 0; c < CSP; c++) ob[(size_t)(c+1)*HWSZ] = r[c];
}

// ---------------------------------------------------------------------------
extern "C" void kernel_launch(void* const* d_in, const int* in_sizes, int n_in,
                              void* d_out, int out_size)
{
    const float* x   = (const float*)d_in[0];
    const float* w1  = (const float*)d_in[1];
    const float* b1  = (const float*)d_in[2];
    const float* g1  = (const float*)d_in[3];
    const float* bt1 = (const float*)d_in[4];
    const float* w2  = (const float*)d_in[5];
    const float* b2  = (const float*)d_in[6];
    const float* g2  = (const float*)d_in[7];
    const float* bt2 = (const float*)d_in[8];
    const float* wp  = (const float*)d_in[9];
    const float* bp  = (const float*)d_in[10];
    const float* gp  = (const float*)d_in[11];
    const float* btp = (const float*)d_in[12];
    float* out = (float*)d_out;

    void *pxh,*ps1,*pyh,*ps2,*psp,*pB1,*pB2,*ppart,*pstats;
    cudaGetSymbolAddress(&pxh, g_xh);
    cudaGetSymbolAddress(&ps1, g_s1);   cudaGetSymbolAddress(&pyh, g_y1h);
    cudaGetSymbolAddress(&ps2, g_s2);
    cudaGetSymbolAddress(&psp, g_spb);  cudaGetSymbolAddress(&pB1, g_B1);
    cudaGetSymbolAddress(&pB2, g_B2);   cudaGetSymbolAddress(&ppart, g_part);
    cudaGetSymbolAddress(&pstats, g_stats);
    ushortt* xh = (ushortt*)pxh;
    float* s1 = (float*)ps1;
    ushortt* yh = (ushortt*)pyh;
    float* s2 = (float*)ps2;
    float* sp = (float*)psp;
    ushortt* B1 = (ushortt*)pB1;
    ushortt* B2 = (ushortt*)pB2;
    float* part  = (float*)ppart;
    float* stats = (float*)pstats;

    // dynamic smem sizes
    const int SM1 = 2560 + 2*(130*80)  + 10*64*80;   // 74,560
    const int SM2 = 2560 + 2*(130*144) + 9*64*128;   // 113,728
    cudaFuncSetAttribute(convmma_k<32,true>,  cudaFuncAttributeMaxDynamicSharedMemorySize, SM1);
    cudaFuncSetAttribute(convmma_k<64,false>, cudaFuncAttributeMaxDynamicSharedMemorySize, SM2);

    splitx_k<<<NPX/256, 256>>>(x, xh);
    splitw_k<<<245, 256>>>(w1, wp, w2, B1, B2);

    // conv1 (taps 0-8) + convp (tap 9) -> s1, sp + partials
    convmma_k<32,true><<<144, 256, SM1>>>(xh, B1, b1, bp, s1, sp,
                                          part + 0*NTILE*64*2, part + 2*NTILE*64*2);
    stats2_k<<<63, 256>>>(part + 0*NTILE*64*2, g1, bt1, stats + 0*64*2,
                          nullptr, nullptr, nullptr, nullptr);
    bnrp_k<<<NPX/256, 256>>>(s1, stats + 0*64*2, yh);

    // conv2 -> s2 + partials
    convmma_k<64,false><<<144, 256, SM2>>>(yh, B2, b2, nullptr, s2, nullptr,
                                           part + 1*NTILE*64*2, nullptr);
    stats2_k<<<126, 256>>>(part + 1*NTILE*64*2, g2, bt2, stats + 1*64*2,
                           part + 2*NTILE*64*2, gp, btp, stats + 2*64*2);

    final_k<<<NPX/256, 256>>>(s2, sp, stats + 1*64*2, stats + 2*64*2, out);
}